// round 1
// baseline (speedup 1.0000x reference)
#include <cuda_runtime.h>
#include <cstddef>

#define BB 32
#define TT 4096
#define HH 256
#define SS 256
#define MM (BB*TT)          // 131072 tokens
#define NCH 64              // chunks over T
#define LCH 64              // chunk length

// ---------------- scratch (static device globals; no allocations) ----------------
__device__ float g_xn[(size_t)MM*HH];     // layernormed x
__device__ float g_u[(size_t)MM*SS];      // u, then states (in place)
__device__ float g_mixed[(size_t)MM*HH];  // gelu(mixed)
__device__ float g_carry[(size_t)BB*NCH*SS];
__device__ float g_S0[(size_t)BB*NCH*SS];
__device__ float g_coeff[SS];
__device__ float g_cL[SS];

// ---------------- helpers ----------------
__device__ __forceinline__ float softplus_f(float x) {
    return fmaxf(x, 0.0f) + log1pf(expf(-fabsf(x)));
}
__device__ __forceinline__ float gelu_tanh(float x) {
    float x3 = x * x * x;
    float t = tanhf(0.7978845608028654f * (x + 0.044715f * x3));
    return 0.5f * x * (1.0f + t);
}

// ---------------- 0. coefficients ----------------
__global__ void setup_kernel(const float* __restrict__ a_diag,
                             const float* __restrict__ g_diag,
                             const float* __restrict__ dt) {
    int s = threadIdx.x;
    if (s >= SS) return;
    float dt_s = softplus_f(dt[s]) + 1e-4f;
    float omega = a_diag[s] * dt_s;
    float decay = expf(-softplus_f(g_diag[s]) * dt_s);
    decay *= decay;                       // damped=True
    float c = decay * cosf(omega);
    g_coeff[s] = c;
    float p = c;                          // c^64 by 6 squarings
    #pragma unroll
    for (int i = 0; i < 6; i++) p = p * p;
    g_cL[s] = p;
}

// ---------------- 1. layernorm (warp per row) ----------------
__global__ void __launch_bounds__(256) ln_kernel(const float* __restrict__ x,
                                                 const float* __restrict__ w,
                                                 const float* __restrict__ b) {
    int warp = threadIdx.x >> 5, lane = threadIdx.x & 31;
    size_t row = (size_t)blockIdx.x * 8 + warp;
    const float4* xr = reinterpret_cast<const float4*>(x + row * HH);
    float4 v0 = xr[lane];
    float4 v1 = xr[lane + 32];
    float sum = v0.x + v0.y + v0.z + v0.w + v1.x + v1.y + v1.z + v1.w;
    float sq  = v0.x*v0.x + v0.y*v0.y + v0.z*v0.z + v0.w*v0.w
              + v1.x*v1.x + v1.y*v1.y + v1.z*v1.z + v1.w*v1.w;
    #pragma unroll
    for (int o = 16; o > 0; o >>= 1) {
        sum += __shfl_xor_sync(0xffffffffu, sum, o);
        sq  += __shfl_xor_sync(0xffffffffu, sq,  o);
    }
    float mu = sum * (1.0f / HH);
    float var = sq * (1.0f / HH) - mu * mu;
    float rs = rsqrtf(var + 1e-5f);

    const float4* w4 = reinterpret_cast<const float4*>(w);
    const float4* b4 = reinterpret_cast<const float4*>(b);
    float4* o4 = reinterpret_cast<float4*>(g_xn + row * HH);
    float4 wv = w4[lane],      bv = b4[lane];
    float4 r;
    r.x = (v0.x - mu) * rs * wv.x + bv.x;
    r.y = (v0.y - mu) * rs * wv.y + bv.y;
    r.z = (v0.z - mu) * rs * wv.z + bv.z;
    r.w = (v0.w - mu) * rs * wv.w + bv.w;
    o4[lane] = r;
    wv = w4[lane + 32]; bv = b4[lane + 32];
    r.x = (v1.x - mu) * rs * wv.x + bv.x;
    r.y = (v1.y - mu) * rs * wv.y + bv.y;
    r.z = (v1.z - mu) * rs * wv.z + bv.z;
    r.w = (v1.w - mu) * rs * wv.w + bv.w;
    o4[lane + 32] = r;
}

// ---------------- 2. fp32 GEMM: C[m,n] = sum_k A[m,k]*W[n,k] (+epilogue) ----------------
// EPI 0: plain.   EPI 1: gelu(acc + aux1[n]*aux2[m,n]).   EPI 2: aux2[m,n] + acc + aux1[n].
template <int EPI>
__global__ void __launch_bounds__(256) gemm_k(const float* __restrict__ A,
                                              const float* __restrict__ W,
                                              float* __restrict__ C,
                                              const float* __restrict__ aux1,
                                              const float* __restrict__ aux2) {
    const int BM = 128, BN = 64, BK = 16, KTOT = 256, NTOT = 256;
    __shared__ float As[BM * BK];   // [m][k]
    __shared__ float Bs[BK * BN];   // [k][n]
    int tid = threadIdx.x;
    int tx = tid & 15, ty = tid >> 4;          // tx: n-dir (16), ty: m-dir (16)
    size_t mblock = (size_t)blockIdx.y * BM;
    int nblock = blockIdx.x * BN;
    const float* Ab = A + mblock * KTOT;
    const float* Wb = W + (size_t)nblock * KTOT;

    float acc[8][4];
    #pragma unroll
    for (int i = 0; i < 8; i++)
        #pragma unroll
        for (int j = 0; j < 4; j++) acc[i][j] = 0.0f;

    int la_m = tid >> 2, la_k = (tid & 3) * 4;     // A loader
    int lb_n = tid & 63, lb_k = (tid >> 6) * 4;    // W loader

    for (int k0 = 0; k0 < KTOT; k0 += BK) {
        #pragma unroll
        for (int i = 0; i < 2; i++) {
            int m = la_m + i * 64;
            float4 v = *reinterpret_cast<const float4*>(Ab + (size_t)m * KTOT + k0 + la_k);
            *reinterpret_cast<float4*>(&As[m * BK + la_k]) = v;
        }
        {
            float4 v = *reinterpret_cast<const float4*>(Wb + (size_t)lb_n * KTOT + k0 + lb_k);
            Bs[(lb_k + 0) * BN + lb_n] = v.x;
            Bs[(lb_k + 1) * BN + lb_n] = v.y;
            Bs[(lb_k + 2) * BN + lb_n] = v.z;
            Bs[(lb_k + 3) * BN + lb_n] = v.w;
        }
        __syncthreads();
        #pragma unroll
        for (int kk = 0; kk < BK; kk++) {
            float a[8], bf[4];
            #pragma unroll
            for (int i = 0; i < 8; i++) a[i] = As[(ty * 8 + i) * BK + kk];
            float4 bv = *reinterpret_cast<const float4*>(&Bs[kk * BN + tx * 4]);
            bf[0] = bv.x; bf[1] = bv.y; bf[2] = bv.z; bf[3] = bv.w;
            #pragma unroll
            for (int i = 0; i < 8; i++)
                #pragma unroll
                for (int j = 0; j < 4; j++) acc[i][j] = fmaf(a[i], bf[j], acc[i][j]);
        }
        __syncthreads();
    }

    int n = nblock + tx * 4;
    #pragma unroll
    for (int i = 0; i < 8; i++) {
        size_t m = mblock + (size_t)ty * 8 + i;
        size_t off = m * NTOT + n;
        float v0 = acc[i][0], v1 = acc[i][1], v2 = acc[i][2], v3 = acc[i][3];
        if (EPI == 1) {
            float4 xn = *reinterpret_cast<const float4*>(aux2 + off);
            float4 dd = *reinterpret_cast<const float4*>(aux1 + n);
            v0 = gelu_tanh(v0 + dd.x * xn.x);
            v1 = gelu_tanh(v1 + dd.y * xn.y);
            v2 = gelu_tanh(v2 + dd.z * xn.z);
            v3 = gelu_tanh(v3 + dd.w * xn.w);
        } else if (EPI == 2) {
            float4 xv = *reinterpret_cast<const float4*>(aux2 + off);
            float4 bb = *reinterpret_cast<const float4*>(aux1 + n);
            v0 = xv.x + v0 + bb.x;
            v1 = xv.y + v1 + bb.y;
            v2 = xv.z + v2 + bb.z;
            v3 = xv.w + v3 + bb.w;
        }
        float4 r; r.x = v0; r.y = v1; r.z = v2; r.w = v3;
        *reinterpret_cast<float4*>(C + off) = r;
    }
}

// ---------------- 3a. per-chunk Horner carries ----------------
__global__ void __launch_bounds__(256) scanA_kernel() {
    int b = blockIdx.y, ch = blockIdx.x, s = threadIdx.x;
    float c = g_coeff[s];
    size_t base = ((size_t)(b * TT + ch * LCH)) * SS + s;
    float acc = 0.0f;
    #pragma unroll 8
    for (int j = 0; j < LCH; j++) acc = fmaf(c, acc, g_u[base + (size_t)j * SS]);
    g_carry[((size_t)b * NCH + ch) * SS + s] = acc;
}

// ---------------- 3b. scan over chunks (also writes final_state) ----------------
__global__ void __launch_bounds__(256) scanB_kernel(const float* __restrict__ state0,
                                                    float* __restrict__ out) {
    int b = blockIdx.x, s = threadIdx.x;
    float cL = g_cL[s];
    float run = state0[b * SS + s];
    for (int ch = 0; ch < NCH; ch++) {
        size_t idx = ((size_t)b * NCH + ch) * SS + s;
        g_S0[idx] = run;
        run = fmaf(cL, run, g_carry[idx]);
    }
    out[(size_t)MM * HH + (size_t)b * SS + s] = run;   // final_state
}

// ---------------- 3c. re-scan with correct chunk-initial state (in place) ----------------
__global__ void __launch_bounds__(256) scanC_kernel() {
    int b = blockIdx.y, ch = blockIdx.x, s = threadIdx.x;
    float c = g_coeff[s];
    float run = g_S0[((size_t)b * NCH + ch) * SS + s];
    size_t base = ((size_t)(b * TT + ch * LCH)) * SS + s;
    #pragma unroll 8
    for (int j = 0; j < LCH; j++) {
        size_t idx = base + (size_t)j * SS;
        run = fmaf(c, run, g_u[idx]);
        g_u[idx] = run;
    }
}

// ---------------- launch ----------------
extern "C" void kernel_launch(void* const* d_in, const int* in_sizes, int n_in,
                              void* d_out, int out_size) {
    const float* x       = (const float*)d_in[0];
    const float* state0  = (const float*)d_in[1];
    const float* its     = (const float*)d_in[2];   // in_to_state   [S,H]
    const float* sth     = (const float*)d_in[3];   // state_to_hidden [H,S]
    const float* direct  = (const float*)d_in[4];
    const float* a_diag  = (const float*)d_in[5];
    const float* g_diag  = (const float*)d_in[6];
    const float* dt      = (const float*)d_in[7];
    const float* norm_w  = (const float*)d_in[8];
    const float* norm_b  = (const float*)d_in[9];
    const float* out_w   = (const float*)d_in[10];  // [H,H]
    const float* out_b   = (const float*)d_in[11];
    float* out = (float*)d_out;

    float *xn, *u, *mixed;
    cudaGetSymbolAddress((void**)&xn,    g_xn);
    cudaGetSymbolAddress((void**)&u,     g_u);
    cudaGetSymbolAddress((void**)&mixed, g_mixed);

    setup_kernel<<<1, 256>>>(a_diag, g_diag, dt);
    ln_kernel<<<MM / 8, 256>>>(x, norm_w, norm_b);

    dim3 ggrid(SS / 64, MM / 128);
    gemm_k<0><<<ggrid, 256>>>(xn, its, u, nullptr, nullptr);

    scanA_kernel<<<dim3(NCH, BB), 256>>>();
    scanB_kernel<<<BB, 256>>>(state0, out);
    scanC_kernel<<<dim3(NCH, BB), 256>>>();

    gemm_k<1><<<ggrid, 256>>>(u, sth, mixed, direct, xn);
    gemm_k<2><<<ggrid, 256>>>(mixed, out_w, out, out_b, x);
}

// round 3
// speedup vs baseline: 1.8469x; 1.8469x over previous
#include <cuda_runtime.h>
#include <cuda_bf16.h>
#include <cstdint>
#include <cstddef>

#define BB 32
#define TT 4096
#define HH 256
#define SS 256
#define MM (BB*TT)          // 131072 tokens
#define NCH 64              // chunks over T
#define LCH 64              // chunk length

// ---------------- scratch (static device globals; no allocations) ----------------
__device__ __nv_bfloat16 g_xn_cat[(size_t)MM*512];   // [hi | lo] layernormed x
__device__ __nv_bfloat16 g_st_cat[(size_t)MM*512];   // [hi | lo] states
__device__ __nv_bfloat16 g_mix_cat[(size_t)MM*512];  // [hi | lo] gelu(mixed)
__device__ float g_u[(size_t)MM*SS];                 // u (fp32, scan operand)
__device__ __nv_bfloat16 g_wcat[(size_t)3*256*768];  // per-weight [W_hi|W_hi|W_lo]
__device__ float g_carry[(size_t)BB*NCH*SS];
__device__ float g_S0[(size_t)BB*NCH*SS];
__device__ float g_coeff[SS];
__device__ float g_cL[SS];

// ---------------- helpers ----------------
__device__ __forceinline__ uint32_t smem_u32(const void* p) {
    uint32_t a;
    asm("{ .reg .u64 t; cvta.to.shared.u64 t, %1; cvt.u32.u64 %0, t; }" : "=r"(a) : "l"(p));
    return a;
}
__device__ __forceinline__ float softplus_f(float x) {
    return fmaxf(x, 0.0f) + log1pf(expf(-fabsf(x)));
}
__device__ __forceinline__ float gelu_tanh(float x) {
    float x3 = x * x * x;
    float t = tanhf(0.7978845608028654f * (x + 0.044715f * x3));
    return 0.5f * x * (1.0f + t);
}
__device__ __forceinline__ unsigned pk2(float a, float b) {
    __nv_bfloat162 t = __floats2bfloat162_rn(a, b);
    return *reinterpret_cast<unsigned*>(&t);
}
__device__ __forceinline__ void unpk2(unsigned h, unsigned l, float& a, float& b) {
    a = __uint_as_float(h << 16) + __uint_as_float(l << 16);
    b = __uint_as_float(h & 0xffff0000u) + __uint_as_float(l & 0xffff0000u);
}

#define CP_ASYNC16(saddr, gptr) \
    asm volatile("cp.async.cg.shared.global [%0], [%1], 16;" :: "r"(saddr), "l"(gptr))
#define CP_COMMIT() asm volatile("cp.async.commit_group;" ::: "memory")
#define CP_WAIT(n)  asm volatile("cp.async.wait_group %0;" :: "n"(n) : "memory")
#define LDMATRIX_X4(r, addr) \
    asm volatile("ldmatrix.sync.aligned.m8n8.x4.shared.b16 {%0,%1,%2,%3}, [%4];" \
        : "=r"((r)[0]), "=r"((r)[1]), "=r"((r)[2]), "=r"((r)[3]) : "r"(addr))
#define MMA_BF16(d, a, b0, b1) \
    asm volatile("mma.sync.aligned.m16n8k16.row.col.f32.bf16.bf16.f32 " \
        "{%0,%1,%2,%3}, {%4,%5,%6,%7}, {%8,%9}, {%0,%1,%2,%3};" \
        : "+f"((d)[0]), "+f"((d)[1]), "+f"((d)[2]), "+f"((d)[3]) \
        : "r"((a)[0]), "r"((a)[1]), "r"((a)[2]), "r"((a)[3]), "r"(b0), "r"(b1))

// ---------------- 0. coefficients ----------------
__global__ void setup_kernel(const float* __restrict__ a_diag,
                             const float* __restrict__ g_diag,
                             const float* __restrict__ dt) {
    int s = threadIdx.x;
    if (s >= SS) return;
    float dt_s = softplus_f(dt[s]) + 1e-4f;
    float omega = a_diag[s] * dt_s;
    float decay = expf(-softplus_f(g_diag[s]) * dt_s);
    decay *= decay;
    float c = decay * cosf(omega);
    g_coeff[s] = c;
    float p = c;
    #pragma unroll
    for (int i = 0; i < 6; i++) p = p * p;
    g_cL[s] = p;
}

// ---------------- 0b. split weights into [W_hi | W_hi | W_lo] bf16 cat ----------------
__global__ void wsplit_kernel(const float* __restrict__ its,
                              const float* __restrict__ sth,
                              const float* __restrict__ ow) {
    int widx = blockIdx.y;
    int n = blockIdx.x;
    int k = threadIdx.x;
    const float* W = (widx == 0) ? its : ((widx == 1) ? sth : ow);
    __nv_bfloat16* dst = g_wcat + (size_t)widx * 256 * 768;
    float v = W[n * 256 + k];
    __nv_bfloat16 h = __float2bfloat16(v);
    float lo = v - __bfloat162float(h);
    dst[(size_t)n * 768 + k] = h;
    dst[(size_t)n * 768 + 256 + k] = h;
    dst[(size_t)n * 768 + 512 + k] = __float2bfloat16(lo);
}

// ---------------- 1. layernorm -> bf16 hi/lo cat ----------------
__global__ void __launch_bounds__(256) ln_kernel(const float* __restrict__ x,
                                                 const float* __restrict__ w,
                                                 const float* __restrict__ b) {
    int warp = threadIdx.x >> 5, lane = threadIdx.x & 31;
    size_t row = (size_t)blockIdx.x * 8 + warp;
    const float4* xr = reinterpret_cast<const float4*>(x + row * HH);
    float4 v0 = xr[lane];
    float4 v1 = xr[lane + 32];
    float sum = v0.x + v0.y + v0.z + v0.w + v1.x + v1.y + v1.z + v1.w;
    float sq  = v0.x*v0.x + v0.y*v0.y + v0.z*v0.z + v0.w*v0.w
              + v1.x*v1.x + v1.y*v1.y + v1.z*v1.z + v1.w*v1.w;
    #pragma unroll
    for (int o = 16; o > 0; o >>= 1) {
        sum += __shfl_xor_sync(0xffffffffu, sum, o);
        sq  += __shfl_xor_sync(0xffffffffu, sq,  o);
    }
    float mu = sum * (1.0f / HH);
    float var = sq * (1.0f / HH) - mu * mu;
    float rs = rsqrtf(var + 1e-5f);

    const float4* w4 = reinterpret_cast<const float4*>(w);
    const float4* b4 = reinterpret_cast<const float4*>(b);
    __nv_bfloat16* cat = g_xn_cat + row * 512;

    #pragma unroll
    for (int half = 0; half < 2; half++) {
        float4 v = half ? v1 : v0;
        int c0 = half * 128 + lane * 4;
        float4 wv = w4[half * 32 + lane], bv = b4[half * 32 + lane];
        float r0 = (v.x - mu) * rs * wv.x + bv.x;
        float r1 = (v.y - mu) * rs * wv.y + bv.y;
        float r2 = (v.z - mu) * rs * wv.z + bv.z;
        float r3 = (v.w - mu) * rs * wv.w + bv.w;
        __nv_bfloat16 h0 = __float2bfloat16(r0), h1 = __float2bfloat16(r1);
        __nv_bfloat16 h2 = __float2bfloat16(r2), h3 = __float2bfloat16(r3);
        uint2 hv;
        hv.x = pk2(r0, r1);
        hv.y = pk2(r2, r3);
        *reinterpret_cast<uint2*>(cat + c0) = hv;
        uint2 lv;
        lv.x = pk2(r0 - __bfloat162float(h0), r1 - __bfloat162float(h1));
        lv.y = pk2(r2 - __bfloat162float(h2), r3 - __bfloat162float(h3));
        *reinterpret_cast<uint2*>(cat + 256 + c0) = lv;
    }
}

// ---------------- 2. bf16x3 HMMA GEMM: C[m,n] = sum_k A[m,k]*W[n,k] ----------------
// A: [M,512] cat (hi 0-255 | lo 256-511). W: [256,768] cat [W_hi|W_hi|W_lo].
// Effective K = 768; chunk c uses A cols (c*32 mod 512 with the hi-wrap), W cols c*32.
// BM=128, BN=128, BK=32. 8 warps: wm=wid&3 (M), wn=wid>>2 (N); warp tile 32x64.
// EPI 0: fp32 C. EPI 1: gelu(acc + direct[n]*xn[m,n]) -> bf16 cat. EPI 2: x + acc + out_b.
template <int EPI>
__global__ void __launch_bounds__(256, 2) gemm_mma(
    const __nv_bfloat16* __restrict__ A,
    const __nv_bfloat16* __restrict__ W,
    float* __restrict__ Cf,
    __nv_bfloat16* __restrict__ Cb,
    const float* __restrict__ auxf,
    const float* __restrict__ auxx,
    const __nv_bfloat16* __restrict__ xncat)
{
    __shared__ __nv_bfloat16 As[2][128][40];
    __shared__ __nv_bfloat16 Bs[2][128][40];
    const int tid = threadIdx.x;
    const int lane = tid & 31, wid = tid >> 5;
    const int wm = wid & 3, wn = wid >> 2;
    const size_t mblock = (size_t)blockIdx.y * 128;
    const int nblock = blockIdx.x * 128;
    const __nv_bfloat16* Arow = A + mblock * 512;
    const __nv_bfloat16* Wrow = W + (size_t)nblock * 768;

    // global->smem loader mapping: each thread: 2 A segs + 2 B segs of 16B
    const int lrow = tid >> 2;          // 0..63
    const int lseg = (tid & 3) * 8;     // bf16 col offset within 32-col chunk

    const uint32_t sA = smem_u32(As), sB = smem_u32(Bs);
    const uint32_t sa0 = sA + (lrow * 40 + lseg) * 2;
    const uint32_t sa1 = sA + ((lrow + 64) * 40 + lseg) * 2;
    const uint32_t sb0 = sB + (lrow * 40 + lseg) * 2;
    const uint32_t sb1 = sB + ((lrow + 64) * 40 + lseg) * 2;

    // ldmatrix per-thread base addresses
    const uint32_t a_fr = sA + ((wm * 32 + (lane & 15)) * 40 + (lane >> 4) * 8) * 2;
    const uint32_t b_fr = sB + ((wn * 64 + ((lane >> 3) & 1) * 8 + (lane & 7)) * 40
                                + (lane >> 4) * 8) * 2;

    float acc[2][8][4];
    #pragma unroll
    for (int i = 0; i < 2; i++)
        #pragma unroll
        for (int j = 0; j < 8; j++)
            #pragma unroll
            for (int q = 0; q < 4; q++) acc[i][j][q] = 0.0f;

    // ---- issue group for chunk c into buffer c&1 ----
    auto issue = [&](int c) {
        const int buf = c & 1;
        const int k768 = c * 32;
        const int acol = (k768 < 512) ? k768 : (k768 - 512);
        const uint32_t bo = buf * 10240;
        const __nv_bfloat16* ga0 = Arow + (size_t)lrow * 512 + acol + lseg;
        const __nv_bfloat16* gb0 = Wrow + (size_t)lrow * 768 + k768 + lseg;
        CP_ASYNC16(sa0 + bo, ga0);
        CP_ASYNC16(sa1 + bo, ga0 + (size_t)64 * 512);
        CP_ASYNC16(sb0 + bo, gb0);
        CP_ASYNC16(sb1 + bo, gb0 + (size_t)64 * 768);
        CP_COMMIT();
    };

    issue(0);
    for (int c = 0; c < 24; c++) {
        if (c < 23) { issue(c + 1); CP_WAIT(1); }
        else        { CP_WAIT(0); }
        __syncthreads();
        const uint32_t ab = a_fr + (c & 1) * 10240;
        const uint32_t bb = b_fr + (c & 1) * 10240;
        #pragma unroll
        for (int ks = 0; ks < 2; ks++) {
            uint32_t af[2][4];
            LDMATRIX_X4(af[0], ab + ks * 32);
            LDMATRIX_X4(af[1], ab + 16 * 80 + ks * 32);
            uint32_t bf[4][4];
            #pragma unroll
            for (int q = 0; q < 4; q++) LDMATRIX_X4(bf[q], bb + q * 16 * 80 + ks * 32);
            #pragma unroll
            for (int mt = 0; mt < 2; mt++)
                #pragma unroll
                for (int nt = 0; nt < 8; nt++) {
                    const int q = nt >> 1, od = nt & 1;
                    MMA_BF16(acc[mt][nt], af[mt], bf[q][od], bf[q][2 + od]);
                }
        }
        __syncthreads();
    }

    // ---- epilogue ----
    #pragma unroll
    for (int mt = 0; mt < 2; mt++) {
        #pragma unroll
        for (int h = 0; h < 2; h++) {
            const size_t mg = mblock + wm * 32 + mt * 16 + (lane >> 2) + h * 8;
            #pragma unroll
            for (int nt = 0; nt < 8; nt++) {
                const int n = nblock + wn * 64 + nt * 8 + (lane & 3) * 2;
                float v0 = acc[mt][nt][h * 2], v1 = acc[mt][nt][h * 2 + 1];
                if (EPI == 0) {
                    float2 o; o.x = v0; o.y = v1;
                    *reinterpret_cast<float2*>(Cf + mg * 256 + n) = o;
                } else if (EPI == 1) {
                    uint32_t hv = *reinterpret_cast<const uint32_t*>(xncat + mg * 512 + n);
                    uint32_t lv = *reinterpret_cast<const uint32_t*>(xncat + mg * 512 + 256 + n);
                    float x0, x1; unpk2(hv, lv, x0, x1);
                    float2 dd = *reinterpret_cast<const float2*>(auxf + n);
                    float o0 = gelu_tanh(v0 + dd.x * x0);
                    float o1 = gelu_tanh(v1 + dd.y * x1);
                    __nv_bfloat16 h0 = __float2bfloat16(o0), h1 = __float2bfloat16(o1);
                    *reinterpret_cast<uint32_t*>(Cb + mg * 512 + n) = pk2(o0, o1);
                    *reinterpret_cast<uint32_t*>(Cb + mg * 512 + 256 + n) =
                        pk2(o0 - __bfloat162float(h0), o1 - __bfloat162float(h1));
                } else {
                    float2 xv = *reinterpret_cast<const float2*>(auxx + mg * 256 + n);
                    float2 bb2 = *reinterpret_cast<const float2*>(auxf + n);
                    float2 o;
                    o.x = xv.x + v0 + bb2.x;
                    o.y = xv.y + v1 + bb2.y;
                    *reinterpret_cast<float2*>(Cf + mg * 256 + n) = o;
                }
            }
        }
    }
}

// ---------------- 3a. per-chunk Horner carries ----------------
__global__ void __launch_bounds__(256) scanA_kernel() {
    int b = blockIdx.y, ch = blockIdx.x, s = threadIdx.x;
    float c = g_coeff[s];
    size_t base = ((size_t)(b * TT + ch * LCH)) * SS + s;
    float acc = 0.0f;
    #pragma unroll 8
    for (int j = 0; j < LCH; j++) acc = fmaf(c, acc, g_u[base + (size_t)j * SS]);
    g_carry[((size_t)b * NCH + ch) * SS + s] = acc;
}

// ---------------- 3b. scan over chunks (also writes final_state) ----------------
__global__ void __launch_bounds__(256) scanB_kernel(const float* __restrict__ state0,
                                                    float* __restrict__ out) {
    int b = blockIdx.x, s = threadIdx.x;
    float cL = g_cL[s];
    float run = state0[b * SS + s];
    for (int ch = 0; ch < NCH; ch++) {
        size_t idx = ((size_t)b * NCH + ch) * SS + s;
        g_S0[idx] = run;
        run = fmaf(cL, run, g_carry[idx]);
    }
    out[(size_t)MM * HH + (size_t)b * SS + s] = run;
}

// ---------------- 3c. re-scan, write states as bf16 hi/lo cat ----------------
__global__ void __launch_bounds__(256) scanC_kernel() {
    int b = blockIdx.y, ch = blockIdx.x, s = threadIdx.x;
    float c = g_coeff[s];
    float run = g_S0[((size_t)b * NCH + ch) * SS + s];
    size_t row0 = (size_t)(b * TT + ch * LCH);
    #pragma unroll 4
    for (int j = 0; j < LCH; j++) {
        size_t row = row0 + j;
        run = fmaf(c, run, g_u[row * SS + s]);
        __nv_bfloat16 h = __float2bfloat16(run);
        g_st_cat[row * 512 + s] = h;
        g_st_cat[row * 512 + 256 + s] = __float2bfloat16(run - __bfloat162float(h));
    }
}

// ---------------- launch ----------------
extern "C" void kernel_launch(void* const* d_in, const int* in_sizes, int n_in,
                              void* d_out, int out_size) {
    const float* x       = (const float*)d_in[0];
    const float* state0  = (const float*)d_in[1];
    const float* its     = (const float*)d_in[2];
    const float* sth     = (const float*)d_in[3];
    const float* direct  = (const float*)d_in[4];
    const float* a_diag  = (const float*)d_in[5];
    const float* g_diag  = (const float*)d_in[6];
    const float* dt      = (const float*)d_in[7];
    const float* norm_w  = (const float*)d_in[8];
    const float* norm_b  = (const float*)d_in[9];
    const float* out_w   = (const float*)d_in[10];
    const float* out_b   = (const float*)d_in[11];
    float* out = (float*)d_out;

    __nv_bfloat16 *xncat, *stcat, *mixcat, *wcat;
    float* u;
    cudaGetSymbolAddress((void**)&xncat,  g_xn_cat);
    cudaGetSymbolAddress((void**)&stcat,  g_st_cat);
    cudaGetSymbolAddress((void**)&mixcat, g_mix_cat);
    cudaGetSymbolAddress((void**)&wcat,   g_wcat);
    cudaGetSymbolAddress((void**)&u,      g_u);

    setup_kernel<<<1, 256>>>(a_diag, g_diag, dt);
    wsplit_kernel<<<dim3(256, 3), 256>>>(its, sth, out_w);
    ln_kernel<<<MM / 8, 256>>>(x, norm_w, norm_b);

    dim3 ggrid(2, MM / 128);   // N/128, M/128
    gemm_mma<0><<<ggrid, 256>>>(xncat, wcat, u, nullptr, nullptr, nullptr, nullptr);

    scanA_kernel<<<dim3(NCH, BB), 256>>>();
    scanB_kernel<<<BB, 256>>>(state0, out);
    scanC_kernel<<<dim3(NCH, BB), 256>>>();

    gemm_mma<1><<<ggrid, 256>>>(stcat, wcat + (size_t)1 * 256 * 768, nullptr, mixcat,
                                direct, nullptr, xncat);
    gemm_mma<2><<<ggrid, 256>>>(mixcat, wcat + (size_t)2 * 256 * 768, out, nullptr,
                                out_b, x, nullptr);
}

// round 4
// speedup vs baseline: 2.0203x; 1.0939x over previous
#include <cuda_runtime.h>
#include <cuda_bf16.h>
#include <cstdint>
#include <cstddef>

#define BB 32
#define TT 4096
#define HH 256
#define SS 256
#define MM (BB*TT)          // 131072 tokens
#define NCH 64              // chunks over T
#define LCH 64              // chunk length

// ---------------- scratch (static device globals; no allocations) ----------------
__device__ __nv_bfloat16 g_xn_cat[(size_t)MM*512];   // [hi | lo] layernormed x
__device__ __nv_bfloat16 g_st_cat[(size_t)MM*512];   // [hi | lo] states
__device__ __nv_bfloat16 g_mix_cat[(size_t)MM*512];  // [hi | lo] gelu(mixed)
__device__ float g_u[(size_t)MM*SS];                 // u (fp32, scan operand)
__device__ __nv_bfloat16 g_wcat[(size_t)3*256*768];  // per-weight [W_hi|W_hi|W_lo]
__device__ float g_carry[(size_t)BB*NCH*SS];
__device__ float g_S0[(size_t)BB*NCH*SS];
__device__ float g_coeff[SS];
__device__ float g_cL[SS];

// ---------------- helpers ----------------
__device__ __forceinline__ uint32_t smem_u32(const void* p) {
    uint32_t a;
    asm("{ .reg .u64 t; cvta.to.shared.u64 t, %1; cvt.u32.u64 %0, t; }" : "=r"(a) : "l"(p));
    return a;
}
__device__ __forceinline__ float softplus_f(float x) {
    return fmaxf(x, 0.0f) + log1pf(expf(-fabsf(x)));
}
__device__ __forceinline__ float gelu_tanh(float x) {
    float x3 = x * x * x;
    float t = tanhf(0.7978845608028654f * (x + 0.044715f * x3));
    return 0.5f * x * (1.0f + t);
}
__device__ __forceinline__ unsigned pk2(float a, float b) {
    __nv_bfloat162 t = __floats2bfloat162_rn(a, b);
    return *reinterpret_cast<unsigned*>(&t);
}
__device__ __forceinline__ void unpk2(unsigned h, unsigned l, float& a, float& b) {
    a = __uint_as_float(h << 16) + __uint_as_float(l << 16);
    b = __uint_as_float(h & 0xffff0000u) + __uint_as_float(l & 0xffff0000u);
}

#define CP_ASYNC16(saddr, gptr) \
    asm volatile("cp.async.cg.shared.global [%0], [%1], 16;" :: "r"(saddr), "l"(gptr))
#define CP_COMMIT() asm volatile("cp.async.commit_group;" ::: "memory")
#define CP_WAIT(n)  asm volatile("cp.async.wait_group %0;" :: "n"(n) : "memory")
#define LDMATRIX_X4(r, addr) \
    asm volatile("ldmatrix.sync.aligned.m8n8.x4.shared.b16 {%0,%1,%2,%3}, [%4];" \
        : "=r"((r)[0]), "=r"((r)[1]), "=r"((r)[2]), "=r"((r)[3]) : "r"(addr))
#define MMA_BF16(d, a, b0, b1) \
    asm volatile("mma.sync.aligned.m16n8k16.row.col.f32.bf16.bf16.f32 " \
        "{%0,%1,%2,%3}, {%4,%5,%6,%7}, {%8,%9}, {%0,%1,%2,%3};" \
        : "+f"((d)[0]), "+f"((d)[1]), "+f"((d)[2]), "+f"((d)[3]) \
        : "r"((a)[0]), "r"((a)[1]), "r"((a)[2]), "r"((a)[3]), "r"(b0), "r"(b1))

// ---------------- 0. coefficients ----------------
__global__ void setup_kernel(const float* __restrict__ a_diag,
                             const float* __restrict__ g_diag,
                             const float* __restrict__ dt) {
    int s = threadIdx.x;
    if (s >= SS) return;
    float dt_s = softplus_f(dt[s]) + 1e-4f;
    float omega = a_diag[s] * dt_s;
    float decay = expf(-softplus_f(g_diag[s]) * dt_s);
    decay *= decay;
    float c = decay * cosf(omega);
    g_coeff[s] = c;
    float p = c;
    #pragma unroll
    for (int i = 0; i < 6; i++) p = p * p;
    g_cL[s] = p;
}

// ---------------- 0b. split weights into [W_hi | W_hi | W_lo] bf16 cat ----------------
__global__ void wsplit_kernel(const float* __restrict__ its,
                              const float* __restrict__ sth,
                              const float* __restrict__ ow) {
    int widx = blockIdx.y;
    int n = blockIdx.x;
    int k = threadIdx.x;
    const float* W = (widx == 0) ? its : ((widx == 1) ? sth : ow);
    __nv_bfloat16* dst = g_wcat + (size_t)widx * 256 * 768;
    float v = W[n * 256 + k];
    __nv_bfloat16 h = __float2bfloat16(v);
    float lo = v - __bfloat162float(h);
    dst[(size_t)n * 768 + k] = h;
    dst[(size_t)n * 768 + 256 + k] = h;
    dst[(size_t)n * 768 + 512 + k] = __float2bfloat16(lo);
}

// ---------------- 1. layernorm -> bf16 hi/lo cat ----------------
__global__ void __launch_bounds__(256) ln_kernel(const float* __restrict__ x,
                                                 const float* __restrict__ w,
                                                 const float* __restrict__ b) {
    int warp = threadIdx.x >> 5, lane = threadIdx.x & 31;
    size_t row = (size_t)blockIdx.x * 8 + warp;
    const float4* xr = reinterpret_cast<const float4*>(x + row * HH);
    float4 v0 = xr[lane];
    float4 v1 = xr[lane + 32];
    float sum = v0.x + v0.y + v0.z + v0.w + v1.x + v1.y + v1.z + v1.w;
    float sq  = v0.x*v0.x + v0.y*v0.y + v0.z*v0.z + v0.w*v0.w
              + v1.x*v1.x + v1.y*v1.y + v1.z*v1.z + v1.w*v1.w;
    #pragma unroll
    for (int o = 16; o > 0; o >>= 1) {
        sum += __shfl_xor_sync(0xffffffffu, sum, o);
        sq  += __shfl_xor_sync(0xffffffffu, sq,  o);
    }
    float mu = sum * (1.0f / HH);
    float var = sq * (1.0f / HH) - mu * mu;
    float rs = rsqrtf(var + 1e-5f);

    const float4* w4 = reinterpret_cast<const float4*>(w);
    const float4* b4 = reinterpret_cast<const float4*>(b);
    __nv_bfloat16* cat = g_xn_cat + row * 512;

    #pragma unroll
    for (int half = 0; half < 2; half++) {
        float4 v = half ? v1 : v0;
        int c0 = half * 128 + lane * 4;
        float4 wv = w4[half * 32 + lane], bv = b4[half * 32 + lane];
        float r0 = (v.x - mu) * rs * wv.x + bv.x;
        float r1 = (v.y - mu) * rs * wv.y + bv.y;
        float r2 = (v.z - mu) * rs * wv.z + bv.z;
        float r3 = (v.w - mu) * rs * wv.w + bv.w;
        __nv_bfloat16 h0 = __float2bfloat16(r0), h1 = __float2bfloat16(r1);
        __nv_bfloat16 h2 = __float2bfloat16(r2), h3 = __float2bfloat16(r3);
        uint2 hv;
        hv.x = pk2(r0, r1);
        hv.y = pk2(r2, r3);
        *reinterpret_cast<uint2*>(cat + c0) = hv;
        uint2 lv;
        lv.x = pk2(r0 - __bfloat162float(h0), r1 - __bfloat162float(h1));
        lv.y = pk2(r2 - __bfloat162float(h2), r3 - __bfloat162float(h3));
        *reinterpret_cast<uint2*>(cat + 256 + c0) = lv;
    }
}

// ---------------- 2. bf16x3 HMMA GEMM, BK=64, 3-stage cp.async pipeline ----------------
// A: [M,512] cat (hi 0-255 | lo 256-511). W: [256,768] cat [W_hi|W_hi|W_lo].
// Effective K = 768 in 12 chunks of 64. BM=128, BN=128. 8 warps (4x2), warp tile 32x64.
// SMEM per stage: A 128x72 bf16 + B 128x72 bf16 = 36864 B; 3 stages = 110592 B (dynamic).
// EPI 0: fp32 C. EPI 1: gelu(acc + direct[n]*xn[m,n]) -> bf16 cat. EPI 2: x + acc + out_b.
#define GSTG  36864
#define GSMEM (3*GSTG)
template <int EPI>
__global__ void __launch_bounds__(256, 2) gemm_mma(
    const __nv_bfloat16* __restrict__ A,
    const __nv_bfloat16* __restrict__ W,
    float* __restrict__ Cf,
    __nv_bfloat16* __restrict__ Cb,
    const float* __restrict__ auxf,
    const float* __restrict__ auxx,
    const __nv_bfloat16* __restrict__ xncat)
{
    extern __shared__ __nv_bfloat16 smem[];
    const uint32_t sbase = smem_u32(smem);
    const int tid = threadIdx.x;
    const int lane = tid & 31, wid = tid >> 5;
    const int wm = wid & 3, wn = wid >> 2;
    const size_t mblock = (size_t)blockIdx.y * 128;
    const int nblock = blockIdx.x * 128;
    const __nv_bfloat16* Arow = A + mblock * 512;
    const __nv_bfloat16* Wrow = W + (size_t)nblock * 768;

    // per-thread ldmatrix base offsets (within a stage)
    const uint32_t a_off = ((wm * 32 + (lane & 15)) * 72 + (lane >> 4) * 8) * 2;
    const uint32_t b_off = 18432 +
        ((wn * 64 + ((lane >> 3) & 1) * 8 + (lane & 7)) * 72 + (lane >> 4) * 8) * 2;

    float acc[2][8][4];
    #pragma unroll
    for (int i = 0; i < 2; i++)
        #pragma unroll
        for (int j = 0; j < 8; j++)
            #pragma unroll
            for (int q = 0; q < 4; q++) acc[i][j][q] = 0.0f;

    // issue chunk c into stage stg: 128 rows x 64 bf16 per operand, 4 cp.async16 each
    auto issue = [&](int c, int stg) {
        const int k64 = c * 64;
        const int acol = (k64 < 512) ? k64 : (k64 - 512);
        const uint32_t so = sbase + stg * GSTG;
        #pragma unroll
        for (int p = 0; p < 4; p++) {
            const int idx = p * 256 + tid;
            const int row = idx >> 3;
            const int seg = (idx & 7) * 8;
            CP_ASYNC16(so + (row * 72 + seg) * 2,
                       Arow + (size_t)row * 512 + acol + seg);
            CP_ASYNC16(so + 18432 + (row * 72 + seg) * 2,
                       Wrow + (size_t)row * 768 + k64 + seg);
        }
        CP_COMMIT();
    };

    issue(0, 0);
    issue(1, 1);

    int stg = 0, nstg = 2;
    for (int c = 0; c < 12; c++) {
        CP_WAIT(1);
        __syncthreads();
        const uint32_t ab = sbase + stg * GSTG + a_off;
        const uint32_t bb = sbase + stg * GSTG + b_off;
        #pragma unroll
        for (int ks = 0; ks < 4; ks++) {
            uint32_t af[2][4];
            LDMATRIX_X4(af[0], ab + ks * 32);
            LDMATRIX_X4(af[1], ab + 2304 + ks * 32);     // +16 rows
            uint32_t bf[4][4];
            #pragma unroll
            for (int q = 0; q < 4; q++) LDMATRIX_X4(bf[q], bb + q * 2304 + ks * 32);
            #pragma unroll
            for (int mt = 0; mt < 2; mt++)
                #pragma unroll
                for (int nt = 0; nt < 8; nt++) {
                    const int q = nt >> 1, od = nt & 1;
                    MMA_BF16(acc[mt][nt], af[mt], bf[q][od], bf[q][2 + od]);
                }
        }
        if (c < 10) issue(c + 2, nstg);
        stg = (stg == 2) ? 0 : stg + 1;
        nstg = (nstg == 2) ? 0 : nstg + 1;
    }

    // ---- epilogue ----
    #pragma unroll
    for (int mt = 0; mt < 2; mt++) {
        #pragma unroll
        for (int h = 0; h < 2; h++) {
            const size_t mg = mblock + wm * 32 + mt * 16 + (lane >> 2) + h * 8;
            #pragma unroll
            for (int nt = 0; nt < 8; nt++) {
                const int n = nblock + wn * 64 + nt * 8 + (lane & 3) * 2;
                float v0 = acc[mt][nt][h * 2], v1 = acc[mt][nt][h * 2 + 1];
                if (EPI == 0) {
                    float2 o; o.x = v0; o.y = v1;
                    *reinterpret_cast<float2*>(Cf + mg * 256 + n) = o;
                } else if (EPI == 1) {
                    uint32_t hv = *reinterpret_cast<const uint32_t*>(xncat + mg * 512 + n);
                    uint32_t lv = *reinterpret_cast<const uint32_t*>(xncat + mg * 512 + 256 + n);
                    float x0, x1; unpk2(hv, lv, x0, x1);
                    float2 dd = *reinterpret_cast<const float2*>(auxf + n);
                    float o0 = gelu_tanh(v0 + dd.x * x0);
                    float o1 = gelu_tanh(v1 + dd.y * x1);
                    __nv_bfloat16 h0 = __float2bfloat16(o0), h1 = __float2bfloat16(o1);
                    *reinterpret_cast<uint32_t*>(Cb + mg * 512 + n) = pk2(o0, o1);
                    *reinterpret_cast<uint32_t*>(Cb + mg * 512 + 256 + n) =
                        pk2(o0 - __bfloat162float(h0), o1 - __bfloat162float(h1));
                } else {
                    float2 xv = *reinterpret_cast<const float2*>(auxx + mg * 256 + n);
                    float2 bb2 = *reinterpret_cast<const float2*>(auxf + n);
                    float2 o;
                    o.x = xv.x + v0 + bb2.x;
                    o.y = xv.y + v1 + bb2.y;
                    *reinterpret_cast<float2*>(Cf + mg * 256 + n) = o;
                }
            }
        }
    }
}

// ---------------- 3a. per-chunk Horner carries ----------------
__global__ void __launch_bounds__(256) scanA_kernel() {
    int b = blockIdx.y, ch = blockIdx.x, s = threadIdx.x;
    float c = g_coeff[s];
    size_t base = ((size_t)(b * TT + ch * LCH)) * SS + s;
    float acc = 0.0f;
    #pragma unroll 8
    for (int j = 0; j < LCH; j++) acc = fmaf(c, acc, g_u[base + (size_t)j * SS]);
    g_carry[((size_t)b * NCH + ch) * SS + s] = acc;
}

// ---------------- 3b. scan over chunks (also writes final_state) ----------------
__global__ void __launch_bounds__(256) scanB_kernel(const float* __restrict__ state0,
                                                    float* __restrict__ out) {
    int b = blockIdx.x, s = threadIdx.x;
    float cL = g_cL[s];
    float run = state0[b * SS + s];
    for (int ch = 0; ch < NCH; ch++) {
        size_t idx = ((size_t)b * NCH + ch) * SS + s;
        g_S0[idx] = run;
        run = fmaf(cL, run, g_carry[idx]);
    }
    out[(size_t)MM * HH + (size_t)b * SS + s] = run;
}

// ---------------- 3c. re-scan, write states as bf16 hi/lo cat ----------------
__global__ void __launch_bounds__(256) scanC_kernel() {
    int b = blockIdx.y, ch = blockIdx.x, s = threadIdx.x;
    float c = g_coeff[s];
    float run = g_S0[((size_t)b * NCH + ch) * SS + s];
    size_t row0 = (size_t)(b * TT + ch * LCH);
    #pragma unroll 4
    for (int j = 0; j < LCH; j++) {
        size_t row = row0 + j;
        run = fmaf(c, run, g_u[row * SS + s]);
        __nv_bfloat16 h = __float2bfloat16(run);
        g_st_cat[row * 512 + s] = h;
        g_st_cat[row * 512 + 256 + s] = __float2bfloat16(run - __bfloat162float(h));
    }
}

// ---------------- launch ----------------
extern "C" void kernel_launch(void* const* d_in, const int* in_sizes, int n_in,
                              void* d_out, int out_size) {
    const float* x       = (const float*)d_in[0];
    const float* state0  = (const float*)d_in[1];
    const float* its     = (const float*)d_in[2];
    const float* sth     = (const float*)d_in[3];
    const float* direct  = (const float*)d_in[4];
    const float* a_diag  = (const float*)d_in[5];
    const float* g_diag  = (const float*)d_in[6];
    const float* dt      = (const float*)d_in[7];
    const float* norm_w  = (const float*)d_in[8];
    const float* norm_b  = (const float*)d_in[9];
    const float* out_w   = (const float*)d_in[10];
    const float* out_b   = (const float*)d_in[11];
    float* out = (float*)d_out;

    __nv_bfloat16 *xncat, *stcat, *mixcat, *wcat;
    float* u;
    cudaGetSymbolAddress((void**)&xncat,  g_xn_cat);
    cudaGetSymbolAddress((void**)&stcat,  g_st_cat);
    cudaGetSymbolAddress((void**)&mixcat, g_mix_cat);
    cudaGetSymbolAddress((void**)&wcat,   g_wcat);
    cudaGetSymbolAddress((void**)&u,      g_u);

    cudaFuncSetAttribute(gemm_mma<0>, cudaFuncAttributeMaxDynamicSharedMemorySize, GSMEM);
    cudaFuncSetAttribute(gemm_mma<1>, cudaFuncAttributeMaxDynamicSharedMemorySize, GSMEM);
    cudaFuncSetAttribute(gemm_mma<2>, cudaFuncAttributeMaxDynamicSharedMemorySize, GSMEM);

    setup_kernel<<<1, 256>>>(a_diag, g_diag, dt);
    wsplit_kernel<<<dim3(256, 3), 256>>>(its, sth, out_w);
    ln_kernel<<<MM / 8, 256>>>(x, norm_w, norm_b);

    dim3 ggrid(2, MM / 128);   // N/128, M/128
    gemm_mma<0><<<ggrid, 256, GSMEM>>>(xncat, wcat, u, nullptr, nullptr, nullptr, nullptr);

    scanA_kernel<<<dim3(NCH, BB), 256>>>();
    scanB_kernel<<<BB, 256>>>(state0, out);
    scanC_kernel<<<dim3(NCH, BB), 256>>>();

    gemm_mma<1><<<ggrid, 256, GSMEM>>>(stcat, wcat + (size_t)1 * 256 * 768, nullptr, mixcat,
                                       direct, nullptr, xncat);
    gemm_mma<2><<<ggrid, 256, GSMEM>>>(mixcat, wcat + (size_t)2 * 256 * 768, out, nullptr,
                                       out_b, x, nullptr);
}

// round 5
// speedup vs baseline: 2.0932x; 1.0361x over previous
#include <cuda_runtime.h>
#include <cuda_bf16.h>
#include <cstdint>
#include <cstddef>

#define BB 32
#define TT 4096
#define HH 256
#define SS 256
#define MM (BB*TT)          // 131072 tokens
#define NCH 64              // chunks over T
#define LCH 64              // chunk length

// ---------------- scratch (static device globals; no allocations) ----------------
__device__ __nv_bfloat16 g_xn_cat[(size_t)MM*512];   // [hi | lo] layernormed x
__device__ __nv_bfloat16 g_st_cat[(size_t)MM*512];   // [hi | lo] states
__device__ __nv_bfloat16 g_mix_cat[(size_t)MM*512];  // [hi | lo] gelu(mixed)
__device__ float g_u[(size_t)MM*SS];                 // u (fp32, scan operand)
__device__ __nv_bfloat16 g_wcat[(size_t)3*256*768];  // per-weight [W_hi|W_hi|W_lo]
__device__ float g_carry[(size_t)BB*NCH*SS];
__device__ float g_S0[(size_t)BB*NCH*SS];
__device__ float g_coeff[SS];
__device__ float g_cL[SS];

// ---------------- helpers ----------------
__device__ __forceinline__ uint32_t smem_u32(const void* p) {
    uint32_t a;
    asm("{ .reg .u64 t; cvta.to.shared.u64 t, %1; cvt.u32.u64 %0, t; }" : "=r"(a) : "l"(p));
    return a;
}
__device__ __forceinline__ float softplus_f(float x) {
    return fmaxf(x, 0.0f) + log1pf(expf(-fabsf(x)));
}
__device__ __forceinline__ float gelu_tanh(float x) {
    float x3 = x * x * x;
    float t = tanhf(0.7978845608028654f * (x + 0.044715f * x3));
    return 0.5f * x * (1.0f + t);
}
__device__ __forceinline__ unsigned pk2(float a, float b) {
    __nv_bfloat162 t = __floats2bfloat162_rn(a, b);
    return *reinterpret_cast<unsigned*>(&t);
}
__device__ __forceinline__ void unpk2(unsigned h, unsigned l, float& a, float& b) {
    a = __uint_as_float(h << 16) + __uint_as_float(l << 16);
    b = __uint_as_float(h & 0xffff0000u) + __uint_as_float(l & 0xffff0000u);
}

#define CP_ASYNC16(saddr, gptr) \
    asm volatile("cp.async.cg.shared.global [%0], [%1], 16;" :: "r"(saddr), "l"(gptr))
#define CP_COMMIT() asm volatile("cp.async.commit_group;" ::: "memory")
#define CP_WAIT(n)  asm volatile("cp.async.wait_group %0;" :: "n"(n) : "memory")
#define LDMATRIX_X4(r, addr) \
    asm volatile("ldmatrix.sync.aligned.m8n8.x4.shared.b16 {%0,%1,%2,%3}, [%4];" \
        : "=r"((r)[0]), "=r"((r)[1]), "=r"((r)[2]), "=r"((r)[3]) : "r"(addr))
#define MMA_BF16(d, a, b0, b1) \
    asm volatile("mma.sync.aligned.m16n8k16.row.col.f32.bf16.bf16.f32 " \
        "{%0,%1,%2,%3}, {%4,%5,%6,%7}, {%8,%9}, {%0,%1,%2,%3};" \
        : "+f"((d)[0]), "+f"((d)[1]), "+f"((d)[2]), "+f"((d)[3]) \
        : "r"((a)[0]), "r"((a)[1]), "r"((a)[2]), "r"((a)[3]), "r"(b0), "r"(b1))

// ---------------- 0. wsplit + coefficients (merged) ----------------
__global__ void wsplit_kernel(const float* __restrict__ its,
                              const float* __restrict__ sth,
                              const float* __restrict__ ow,
                              const float* __restrict__ a_diag,
                              const float* __restrict__ g_diag,
                              const float* __restrict__ dt) {
    int widx = blockIdx.y;
    int n = blockIdx.x;
    int k = threadIdx.x;
    if (widx == 0 && n == 0) {   // coefficient setup piggybacks on one block
        int s = k;
        float dt_s = softplus_f(dt[s]) + 1e-4f;
        float omega = a_diag[s] * dt_s;
        float decay = expf(-softplus_f(g_diag[s]) * dt_s);
        decay *= decay;
        float c = decay * cosf(omega);
        g_coeff[s] = c;
        float p = c;
        #pragma unroll
        for (int i = 0; i < 6; i++) p = p * p;
        g_cL[s] = p;
    }
    const float* W = (widx == 0) ? its : ((widx == 1) ? sth : ow);
    __nv_bfloat16* dst = g_wcat + (size_t)widx * 256 * 768;
    float v = W[n * 256 + k];
    __nv_bfloat16 h = __float2bfloat16(v);
    float lo = v - __bfloat162float(h);
    dst[(size_t)n * 768 + k] = h;
    dst[(size_t)n * 768 + 256 + k] = h;
    dst[(size_t)n * 768 + 512 + k] = __float2bfloat16(lo);
}

// ---------------- 1. layernorm -> bf16 hi/lo cat ----------------
__global__ void __launch_bounds__(256) ln_kernel(const float* __restrict__ x,
                                                 const float* __restrict__ w,
                                                 const float* __restrict__ b) {
    int warp = threadIdx.x >> 5, lane = threadIdx.x & 31;
    size_t row = (size_t)blockIdx.x * 8 + warp;
    const float4* xr = reinterpret_cast<const float4*>(x + row * HH);
    float4 v0 = xr[lane];
    float4 v1 = xr[lane + 32];
    float sum = v0.x + v0.y + v0.z + v0.w + v1.x + v1.y + v1.z + v1.w;
    float sq  = v0.x*v0.x + v0.y*v0.y + v0.z*v0.z + v0.w*v0.w
              + v1.x*v1.x + v1.y*v1.y + v1.z*v1.z + v1.w*v1.w;
    #pragma unroll
    for (int o = 16; o > 0; o >>= 1) {
        sum += __shfl_xor_sync(0xffffffffu, sum, o);
        sq  += __shfl_xor_sync(0xffffffffu, sq,  o);
    }
    float mu = sum * (1.0f / HH);
    float var = sq * (1.0f / HH) - mu * mu;
    float rs = rsqrtf(var + 1e-5f);

    const float4* w4 = reinterpret_cast<const float4*>(w);
    const float4* b4 = reinterpret_cast<const float4*>(b);
    __nv_bfloat16* cat = g_xn_cat + row * 512;

    #pragma unroll
    for (int half = 0; half < 2; half++) {
        float4 v = half ? v1 : v0;
        int c0 = half * 128 + lane * 4;
        float4 wv = w4[half * 32 + lane], bv = b4[half * 32 + lane];
        float r0 = (v.x - mu) * rs * wv.x + bv.x;
        float r1 = (v.y - mu) * rs * wv.y + bv.y;
        float r2 = (v.z - mu) * rs * wv.z + bv.z;
        float r3 = (v.w - mu) * rs * wv.w + bv.w;
        __nv_bfloat16 h0 = __float2bfloat16(r0), h1 = __float2bfloat16(r1);
        __nv_bfloat16 h2 = __float2bfloat16(r2), h3 = __float2bfloat16(r3);
        uint2 hv;
        hv.x = pk2(r0, r1);
        hv.y = pk2(r2, r3);
        *reinterpret_cast<uint2*>(cat + c0) = hv;
        uint2 lv;
        lv.x = pk2(r0 - __bfloat162float(h0), r1 - __bfloat162float(h1));
        lv.y = pk2(r2 - __bfloat162float(h2), r3 - __bfloat162float(h3));
        *reinterpret_cast<uint2*>(cat + 256 + c0) = lv;
    }
}

// ---------------- 2. bf16x3 HMMA GEMM, BK=64, 3-stage, fully unrolled ----------------
// A: [M,512] cat (hi 0-255 | lo 256-511). W: [256,768] cat [W_hi|W_hi|W_lo].
// K_eff = 768 in 12 chunks of 64. BM=128, BN=128. 8 warps (4x2), warp tile 32x64.
// Stage: A 128x72 bf16 + B 128x72 bf16 = 36864 B; 3 stages (dynamic smem).
// EPI 0: fp32 C. EPI 1: gelu(acc + direct[n]*xn[m,n]) -> bf16 cat. EPI 2: x + acc + out_b.
#define GSTG  36864
#define GSMEM (3*GSTG)
template <int EPI>
__global__ void __launch_bounds__(256, 2) gemm_mma(
    const __nv_bfloat16* __restrict__ A,
    const __nv_bfloat16* __restrict__ W,
    float* __restrict__ Cf,
    __nv_bfloat16* __restrict__ Cb,
    const float* __restrict__ auxf,
    const float* __restrict__ auxx,
    const __nv_bfloat16* __restrict__ xncat)
{
    extern __shared__ __nv_bfloat16 smem[];
    const uint32_t sbase = smem_u32(smem);
    const int tid = threadIdx.x;
    const int lane = tid & 31, wid = tid >> 5;
    const int wm = wid & 3, wn = wid >> 2;
    const size_t mblock = (size_t)blockIdx.y * 128;
    const int nblock = blockIdx.x * 128;

    // loader mapping: thread handles 4 (row,seg) pairs per operand per chunk
    const int lrow = tid >> 3;            // 0..31  (row, +32 per p)
    const int lseg = (tid & 7) * 8;       // bf16 col offset in 64-col chunk
    // per-thread global base pointers (chunk offset added as immediate)
    const __nv_bfloat16* gA = A + (mblock + lrow) * 512 + lseg;
    const __nv_bfloat16* gW = W + (size_t)(nblock + lrow) * 768 + lseg;
    const uint32_t sAw = sbase + (lrow * 72 + lseg) * 2;           // A smem write base
    const uint32_t sBw = sbase + 18432 + (lrow * 72 + lseg) * 2;   // B smem write base

    // per-thread ldmatrix base offsets (within a stage)
    const uint32_t a_off = sbase + ((wm * 32 + (lane & 15)) * 72 + (lane >> 4) * 8) * 2;
    const uint32_t b_off = sbase + 18432 +
        ((wn * 64 + ((lane >> 3) & 1) * 8 + (lane & 7)) * 72 + (lane >> 4) * 8) * 2;

    float acc[2][8][4];
    #pragma unroll
    for (int i = 0; i < 2; i++)
        #pragma unroll
        for (int j = 0; j < 8; j++)
            #pragma unroll
            for (int q = 0; q < 4; q++) acc[i][j][q] = 0.0f;

    // macro-ish issue: c and stg compile-time after unroll
    auto issue = [&](int c, int stg) {
        const int k64 = c * 64;
        const int acol = (k64 < 512) ? k64 : (k64 - 512);
        const uint32_t so = (uint32_t)stg * GSTG;
        #pragma unroll
        for (int p = 0; p < 4; p++) {
            CP_ASYNC16(sAw + so + p * 32 * 144, gA + (size_t)p * 32 * 512 + acol);
            CP_ASYNC16(sBw + so + p * 32 * 144, gW + (size_t)p * 32 * 768 + k64);
        }
        CP_COMMIT();
    };

    issue(0, 0);
    issue(1, 1);

    #pragma unroll
    for (int c = 0; c < 12; c++) {
        const int stg = c % 3;
        CP_WAIT(1);
        __syncthreads();
        if (c < 10) issue(c + 2, (c + 2) % 3);   // DMA overlaps this chunk's MMAs
        const uint32_t ab = a_off + stg * GSTG;
        const uint32_t bb = b_off + stg * GSTG;
        #pragma unroll
        for (int ks = 0; ks < 4; ks++) {
            uint32_t af[2][4];
            LDMATRIX_X4(af[0], ab + ks * 32);
            LDMATRIX_X4(af[1], ab + 2304 + ks * 32);     // +16 rows
            uint32_t bf[4][4];
            #pragma unroll
            for (int q = 0; q < 4; q++) LDMATRIX_X4(bf[q], bb + q * 2304 + ks * 32);
            #pragma unroll
            for (int mt = 0; mt < 2; mt++)
                #pragma unroll
                for (int nt = 0; nt < 8; nt++) {
                    const int q = nt >> 1, od = nt & 1;
                    MMA_BF16(acc[mt][nt], af[mt], bf[q][od], bf[q][2 + od]);
                }
        }
    }

    // ---- epilogue ----
    #pragma unroll
    for (int mt = 0; mt < 2; mt++) {
        #pragma unroll
        for (int h = 0; h < 2; h++) {
            const size_t mg = mblock + wm * 32 + mt * 16 + (lane >> 2) + h * 8;
            #pragma unroll
            for (int nt = 0; nt < 8; nt++) {
                const int n = nblock + wn * 64 + nt * 8 + (lane & 3) * 2;
                float v0 = acc[mt][nt][h * 2], v1 = acc[mt][nt][h * 2 + 1];
                if (EPI == 0) {
                    float2 o; o.x = v0; o.y = v1;
                    *reinterpret_cast<float2*>(Cf + mg * 256 + n) = o;
                } else if (EPI == 1) {
                    uint32_t hv = *reinterpret_cast<const uint32_t*>(xncat + mg * 512 + n);
                    uint32_t lv = *reinterpret_cast<const uint32_t*>(xncat + mg * 512 + 256 + n);
                    float x0, x1; unpk2(hv, lv, x0, x1);
                    float2 dd = *reinterpret_cast<const float2*>(auxf + n);
                    float o0 = gelu_tanh(v0 + dd.x * x0);
                    float o1 = gelu_tanh(v1 + dd.y * x1);
                    __nv_bfloat16 h0 = __float2bfloat16(o0), h1 = __float2bfloat16(o1);
                    *reinterpret_cast<uint32_t*>(Cb + mg * 512 + n) = pk2(o0, o1);
                    *reinterpret_cast<uint32_t*>(Cb + mg * 512 + 256 + n) =
                        pk2(o0 - __bfloat162float(h0), o1 - __bfloat162float(h1));
                } else {
                    float2 xv = *reinterpret_cast<const float2*>(auxx + mg * 256 + n);
                    float2 bb2 = *reinterpret_cast<const float2*>(auxf + n);
                    float2 o;
                    o.x = xv.x + v0 + bb2.x;
                    o.y = xv.y + v1 + bb2.y;
                    *reinterpret_cast<float2*>(Cf + mg * 256 + n) = o;
                }
            }
        }
    }
}

// ---------------- 3a. per-chunk Horner carries ----------------
__global__ void __launch_bounds__(256) scanA_kernel() {
    int b = blockIdx.y, ch = blockIdx.x, s = threadIdx.x;
    float c = g_coeff[s];
    size_t base = ((size_t)(b * TT + ch * LCH)) * SS + s;
    float acc = 0.0f;
    #pragma unroll 8
    for (int j = 0; j < LCH; j++) acc = fmaf(c, acc, g_u[base + (size_t)j * SS]);
    g_carry[((size_t)b * NCH + ch) * SS + s] = acc;
}

// ---------------- 3b. scan over chunks (also writes final_state) ----------------
__global__ void __launch_bounds__(256) scanB_kernel(const float* __restrict__ state0,
                                                    float* __restrict__ out) {
    int b = blockIdx.x, s = threadIdx.x;
    float cL = g_cL[s];
    float run = state0[b * SS + s];
    for (int ch = 0; ch < NCH; ch++) {
        size_t idx = ((size_t)b * NCH + ch) * SS + s;
        g_S0[idx] = run;
        run = fmaf(cL, run, g_carry[idx]);
    }
    out[(size_t)MM * HH + (size_t)b * SS + s] = run;
}

// ---------------- 3c. re-scan, write states as bf16 hi/lo cat ----------------
__global__ void __launch_bounds__(256) scanC_kernel() {
    int b = blockIdx.y, ch = blockIdx.x, s = threadIdx.x;
    float c = g_coeff[s];
    float run = g_S0[((size_t)b * NCH + ch) * SS + s];
    size_t row0 = (size_t)(b * TT + ch * LCH);
    #pragma unroll 4
    for (int j = 0; j < LCH; j++) {
        size_t row = row0 + j;
        run = fmaf(c, run, g_u[row * SS + s]);
        __nv_bfloat16 h = __float2bfloat16(run);
        g_st_cat[row * 512 + s] = h;
        g_st_cat[row * 512 + 256 + s] = __float2bfloat16(run - __bfloat162float(h));
    }
}

// ---------------- launch ----------------
extern "C" void kernel_launch(void* const* d_in, const int* in_sizes, int n_in,
                              void* d_out, int out_size) {
    const float* x       = (const float*)d_in[0];
    const float* state0  = (const float*)d_in[1];
    const float* its     = (const float*)d_in[2];
    const float* sth     = (const float*)d_in[3];
    const float* direct  = (const float*)d_in[4];
    const float* a_diag  = (const float*)d_in[5];
    const float* g_diag  = (const float*)d_in[6];
    const float* dt      = (const float*)d_in[7];
    const float* norm_w  = (const float*)d_in[8];
    const float* norm_b  = (const float*)d_in[9];
    const float* out_w   = (const float*)d_in[10];
    const float* out_b   = (const float*)d_in[11];
    float* out = (float*)d_out;

    __nv_bfloat16 *xncat, *stcat, *mixcat, *wcat;
    float* u;
    cudaGetSymbolAddress((void**)&xncat,  g_xn_cat);
    cudaGetSymbolAddress((void**)&stcat,  g_st_cat);
    cudaGetSymbolAddress((void**)&mixcat, g_mix_cat);
    cudaGetSymbolAddress((void**)&wcat,   g_wcat);
    cudaGetSymbolAddress((void**)&u,      g_u);

    cudaFuncSetAttribute(gemm_mma<0>, cudaFuncAttributeMaxDynamicSharedMemorySize, GSMEM);
    cudaFuncSetAttribute(gemm_mma<1>, cudaFuncAttributeMaxDynamicSharedMemorySize, GSMEM);
    cudaFuncSetAttribute(gemm_mma<2>, cudaFuncAttributeMaxDynamicSharedMemorySize, GSMEM);

    wsplit_kernel<<<dim3(256, 3), 256>>>(its, sth, out_w, a_diag, g_diag, dt);
    ln_kernel<<<MM / 8, 256>>>(x, norm_w, norm_b);

    dim3 ggrid(2, MM / 128);   // N/128, M/128
    gemm_mma<0><<<ggrid, 256, GSMEM>>>(xncat, wcat, u, nullptr, nullptr, nullptr, nullptr);

    scanA_kernel<<<dim3(NCH, BB), 256>>>();
    scanB_kernel<<<BB, 256>>>(state0, out);
    scanC_kernel<<<dim3(NCH, BB), 256>>>();

    gemm_mma<1><<<ggrid, 256, GSMEM>>>(stcat, wcat + (size_t)1 * 256 * 768, nullptr, mixcat,
                                       direct, nullptr, xncat);
    gemm_mma<2><<<ggrid, 256, GSMEM>>>(mixcat, wcat + (size_t)2 * 256 * 768, out, nullptr,
                                       out_b, x, nullptr);
}

// round 6
// speedup vs baseline: 2.1176x; 1.0117x over previous
#include <cuda_runtime.h>
#include <cuda_bf16.h>
#include <cstdint>
#include <cstddef>

#define BB 32
#define TT 4096
#define HH 256
#define SS 256
#define MM (BB*TT)          // 131072 tokens
#define NCH 64              // chunks over T
#define LCH 64              // chunk length

// ---------------- scratch (static device globals; no allocations) ----------------
__device__ __nv_bfloat16 g_xn_cat[(size_t)MM*512];   // [hi | lo] layernormed x
__device__ __nv_bfloat16 g_st_cat[(size_t)MM*512];   // [hi | lo] states
__device__ __nv_bfloat16 g_mix_cat[(size_t)MM*512];  // [hi | lo] gelu(mixed)
__device__ float g_u[(size_t)MM*SS];                 // u (fp32, scan operand)
__device__ __nv_bfloat16 g_wcat[(size_t)3*256*768];  // per-weight [W_hi|W_hi|W_lo]
__device__ float g_carry[(size_t)BB*NCH*SS];
__device__ float g_S0[(size_t)BB*NCH*SS];
__device__ float g_coeff[SS];
__device__ float g_cL[SS];

// ---------------- helpers ----------------
__device__ __forceinline__ uint32_t smem_u32(const void* p) {
    uint32_t a;
    asm("{ .reg .u64 t; cvta.to.shared.u64 t, %1; cvt.u32.u64 %0, t; }" : "=r"(a) : "l"(p));
    return a;
}
__device__ __forceinline__ float softplus_f(float x) {
    return fmaxf(x, 0.0f) + log1pf(expf(-fabsf(x)));
}
__device__ __forceinline__ float gelu_tanh(float x) {
    float x3 = x * x * x;
    float t = tanhf(0.7978845608028654f * (x + 0.044715f * x3));
    return 0.5f * x * (1.0f + t);
}
__device__ __forceinline__ unsigned pk2(float a, float b) {
    __nv_bfloat162 t = __floats2bfloat162_rn(a, b);
    return *reinterpret_cast<unsigned*>(&t);
}
__device__ __forceinline__ void unpk2(unsigned h, unsigned l, float& a, float& b) {
    a = __uint_as_float(h << 16) + __uint_as_float(l << 16);
    b = __uint_as_float(h & 0xffff0000u) + __uint_as_float(l & 0xffff0000u);
}

#define CP_ASYNC16(saddr, gptr) \
    asm volatile("cp.async.cg.shared.global [%0], [%1], 16;" :: "r"(saddr), "l"(gptr))
#define CP_COMMIT() asm volatile("cp.async.commit_group;" ::: "memory")
#define CP_WAIT(n)  asm volatile("cp.async.wait_group %0;" :: "n"(n) : "memory")
#define LDMATRIX_X4(r, addr) \
    asm volatile("ldmatrix.sync.aligned.m8n8.x4.shared.b16 {%0,%1,%2,%3}, [%4];" \
        : "=r"((r)[0]), "=r"((r)[1]), "=r"((r)[2]), "=r"((r)[3]) : "r"(addr))
#define MMA_BF16(d, a, b0, b1) \
    asm volatile("mma.sync.aligned.m16n8k16.row.col.f32.bf16.bf16.f32 " \
        "{%0,%1,%2,%3}, {%4,%5,%6,%7}, {%8,%9}, {%0,%1,%2,%3};" \
        : "+f"((d)[0]), "+f"((d)[1]), "+f"((d)[2]), "+f"((d)[3]) \
        : "r"((a)[0]), "r"((a)[1]), "r"((a)[2]), "r"((a)[3]), "r"(b0), "r"(b1))

// ---------------- 0. wsplit + coefficients (merged) ----------------
__global__ void wsplit_kernel(const float* __restrict__ its,
                              const float* __restrict__ sth,
                              const float* __restrict__ ow,
                              const float* __restrict__ a_diag,
                              const float* __restrict__ g_diag,
                              const float* __restrict__ dt) {
    int widx = blockIdx.y;
    int n = blockIdx.x;
    int k = threadIdx.x;
    if (widx == 0 && n == 0) {
        int s = k;
        float dt_s = softplus_f(dt[s]) + 1e-4f;
        float omega = a_diag[s] * dt_s;
        float decay = expf(-softplus_f(g_diag[s]) * dt_s);
        decay *= decay;
        float c = decay * cosf(omega);
        g_coeff[s] = c;
        float p = c;
        #pragma unroll
        for (int i = 0; i < 6; i++) p = p * p;
        g_cL[s] = p;
    }
    const float* W = (widx == 0) ? its : ((widx == 1) ? sth : ow);
    __nv_bfloat16* dst = g_wcat + (size_t)widx * 256 * 768;
    float v = W[n * 256 + k];
    __nv_bfloat16 h = __float2bfloat16(v);
    float lo = v - __bfloat162float(h);
    dst[(size_t)n * 768 + k] = h;
    dst[(size_t)n * 768 + 256 + k] = h;
    dst[(size_t)n * 768 + 512 + k] = __float2bfloat16(lo);
}

// ---------------- 1. layernorm -> bf16 hi/lo cat ----------------
__global__ void __launch_bounds__(256) ln_kernel(const float* __restrict__ x,
                                                 const float* __restrict__ w,
                                                 const float* __restrict__ b) {
    int warp = threadIdx.x >> 5, lane = threadIdx.x & 31;
    size_t row = (size_t)blockIdx.x * 8 + warp;
    const float4* xr = reinterpret_cast<const float4*>(x + row * HH);
    float4 v0 = xr[lane];
    float4 v1 = xr[lane + 32];
    float sum = v0.x + v0.y + v0.z + v0.w + v1.x + v1.y + v1.z + v1.w;
    float sq  = v0.x*v0.x + v0.y*v0.y + v0.z*v0.z + v0.w*v0.w
              + v1.x*v1.x + v1.y*v1.y + v1.z*v1.z + v1.w*v1.w;
    #pragma unroll
    for (int o = 16; o > 0; o >>= 1) {
        sum += __shfl_xor_sync(0xffffffffu, sum, o);
        sq  += __shfl_xor_sync(0xffffffffu, sq,  o);
    }
    float mu = sum * (1.0f / HH);
    float var = sq * (1.0f / HH) - mu * mu;
    float rs = rsqrtf(var + 1e-5f);

    const float4* w4 = reinterpret_cast<const float4*>(w);
    const float4* b4 = reinterpret_cast<const float4*>(b);
    __nv_bfloat16* cat = g_xn_cat + row * 512;

    #pragma unroll
    for (int half = 0; half < 2; half++) {
        float4 v = half ? v1 : v0;
        int c0 = half * 128 + lane * 4;
        float4 wv = w4[half * 32 + lane], bv = b4[half * 32 + lane];
        float r0 = (v.x - mu) * rs * wv.x + bv.x;
        float r1 = (v.y - mu) * rs * wv.y + bv.y;
        float r2 = (v.z - mu) * rs * wv.z + bv.z;
        float r3 = (v.w - mu) * rs * wv.w + bv.w;
        __nv_bfloat16 h0 = __float2bfloat16(r0), h1 = __float2bfloat16(r1);
        __nv_bfloat16 h2 = __float2bfloat16(r2), h3 = __float2bfloat16(r3);
        uint2 hv;
        hv.x = pk2(r0, r1);
        hv.y = pk2(r2, r3);
        *reinterpret_cast<uint2*>(cat + c0) = hv;
        uint2 lv;
        lv.x = pk2(r0 - __bfloat162float(h0), r1 - __bfloat162float(h1));
        lv.y = pk2(r2 - __bfloat162float(h2), r3 - __bfloat162float(h3));
        *reinterpret_cast<uint2*>(cat + 256 + c0) = lv;
    }
}

// ---------------- 2. bf16x3 HMMA GEMM, A-tile-reuse ordering, 3+3-slot pipeline ----
// A: [M,512] cat (8 tiles of 64 cols: hi 0-3, lo 4-7). W: [256,768] cat [Whi|Whi|Wlo].
// Step order pairs each A_hi tile with its W_hi and W_lo steps so A loads drop 12->8:
//   steps: (A0,W0)(A0,W512)(A1,W64)(A1,W576)(A2,W128)(A2,W640)(A3,W192)(A3,W704)
//          (A4,W256)(A5,W320)(A6,W384)(A7,W448)
// SMEM: 3 A slots + 3 W slots, 18432 B each (128x72 bf16). Total 110592 B.
// EPI 0: fp32 C + fused per-chunk scan carries. EPI 1: gelu(acc + d[n]*xn) -> cat.
// EPI 2: x + acc + out_b.
#define GSLOT 18432
#define GSMEM (6*GSLOT)
template <int EPI>
__global__ void __launch_bounds__(256, 2) gemm_mma(
    const __nv_bfloat16* __restrict__ A,
    const __nv_bfloat16* __restrict__ W,
    float* __restrict__ Cf,
    __nv_bfloat16* __restrict__ Cb,
    const float* __restrict__ auxf,
    const float* __restrict__ auxx,
    const __nv_bfloat16* __restrict__ xncat)
{
    extern __shared__ __nv_bfloat16 smem[];
    const uint32_t sbase = smem_u32(smem);
    const int tid = threadIdx.x;
    const int lane = tid & 31, wid = tid >> 5;
    const int wm = wid & 3, wn = wid >> 2;
    const size_t mblock = (size_t)blockIdx.y * 128;
    const int nblock = blockIdx.x * 128;

    constexpr int ATILE[12] = {0,0,1,1,2,2,3,3,4,5,6,7};
    constexpr int WCOL[12]  = {0,512,64,576,128,640,192,704,256,320,384,448};

    // loader mapping: thread handles 4 (row,seg) pairs per tile
    const int lrow = tid >> 3;            // 0..31  (+32 per p)
    const int lseg = (tid & 7) * 8;
    const __nv_bfloat16* gA = A + (mblock + lrow) * 512 + lseg;
    const __nv_bfloat16* gW = W + (size_t)(nblock + lrow) * 768 + lseg;
    const uint32_t sAw = sbase + (lrow * 72 + lseg) * 2;
    const uint32_t sBw = sbase + 3*GSLOT + (lrow * 72 + lseg) * 2;

    // per-thread ldmatrix base offsets (within a slot)
    const uint32_t a_off = sbase + ((wm * 32 + (lane & 15)) * 72 + (lane >> 4) * 8) * 2;
    const uint32_t b_off = sbase + 3*GSLOT +
        ((wn * 64 + ((lane >> 3) & 1) * 8 + (lane & 7)) * 72 + (lane >> 4) * 8) * 2;

    float acc[2][8][4];
    #pragma unroll
    for (int i = 0; i < 2; i++)
        #pragma unroll
        for (int j = 0; j < 8; j++)
            #pragma unroll
            for (int q = 0; q < 4; q++) acc[i][j][q] = 0.0f;

    // issue group for step t: W tile always; A tile only when it changes
    auto issue_step = [&](int t) {
        const uint32_t wso = (uint32_t)(t % 3) * GSLOT;
        const int wc = WCOL[t];
        #pragma unroll
        for (int p = 0; p < 4; p++)
            CP_ASYNC16(sBw + wso + p * 4608, gW + (size_t)p * 32 * 768 + wc);
        if (t == 0 || ATILE[t] != ATILE[t - 1]) {
            const int at = ATILE[t];
            const uint32_t aso = (uint32_t)(at % 3) * GSLOT;
            #pragma unroll
            for (int p = 0; p < 4; p++)
                CP_ASYNC16(sAw + aso + p * 4608, gA + (size_t)p * 32 * 512 + at * 64);
        }
        CP_COMMIT();
    };

    issue_step(0);
    issue_step(1);

    #pragma unroll
    for (int c = 0; c < 12; c++) {
        if (c < 11) { CP_WAIT(1); } else { CP_WAIT(0); }
        __syncthreads();
        if (c < 10) issue_step(c + 2);
        const uint32_t ab = a_off + (ATILE[c] % 3) * GSLOT;
        const uint32_t bb = b_off + (c % 3) * GSLOT;
        #pragma unroll
        for (int ks = 0; ks < 4; ks++) {
            uint32_t af[2][4];
            LDMATRIX_X4(af[0], ab + ks * 32);
            LDMATRIX_X4(af[1], ab + 2304 + ks * 32);     // +16 rows
            uint32_t bf[4][4];
            #pragma unroll
            for (int q = 0; q < 4; q++) LDMATRIX_X4(bf[q], bb + q * 2304 + ks * 32);
            #pragma unroll
            for (int mt = 0; mt < 2; mt++)
                #pragma unroll
                for (int nt = 0; nt < 8; nt++) {
                    const int q = nt >> 1, od = nt & 1;
                    MMA_BF16(acc[mt][nt], af[mt], bf[q][od], bf[q][2 + od]);
                }
        }
    }

    if (EPI == 0) __syncthreads();   // mainloop reads done before smem reuse
    float* su = reinterpret_cast<float*>(smem);   // [128][128] u tile (EPI 0)

    // ---- epilogue ----
    #pragma unroll
    for (int mt = 0; mt < 2; mt++) {
        #pragma unroll
        for (int h = 0; h < 2; h++) {
            const int ml = wm * 32 + mt * 16 + (lane >> 2) + h * 8;
            const size_t mg = mblock + ml;
            #pragma unroll
            for (int nt = 0; nt < 8; nt++) {
                const int nl = wn * 64 + nt * 8 + (lane & 3) * 2;
                const int n = nblock + nl;
                float v0 = acc[mt][nt][h * 2], v1 = acc[mt][nt][h * 2 + 1];
                if (EPI == 0) {
                    float2 o; o.x = v0; o.y = v1;
                    *reinterpret_cast<float2*>(Cf + mg * 256 + n) = o;
                    *reinterpret_cast<float2*>(su + ml * 128 + nl) = o;
                } else if (EPI == 1) {
                    uint32_t hv = *reinterpret_cast<const uint32_t*>(xncat + mg * 512 + n);
                    uint32_t lv = *reinterpret_cast<const uint32_t*>(xncat + mg * 512 + 256 + n);
                    float x0, x1; unpk2(hv, lv, x0, x1);
                    float2 dd = *reinterpret_cast<const float2*>(auxf + n);
                    float o0 = gelu_tanh(v0 + dd.x * x0);
                    float o1 = gelu_tanh(v1 + dd.y * x1);
                    __nv_bfloat16 h0 = __float2bfloat16(o0), h1 = __float2bfloat16(o1);
                    *reinterpret_cast<uint32_t*>(Cb + mg * 512 + n) = pk2(o0, o1);
                    *reinterpret_cast<uint32_t*>(Cb + mg * 512 + 256 + n) =
                        pk2(o0 - __bfloat162float(h0), o1 - __bfloat162float(h1));
                } else {
                    float2 xv = *reinterpret_cast<const float2*>(auxx + mg * 256 + n);
                    float2 bb2 = *reinterpret_cast<const float2*>(auxf + n);
                    float2 o;
                    o.x = xv.x + v0 + bb2.x;
                    o.y = xv.y + v1 + bb2.y;
                    *reinterpret_cast<float2*>(Cf + mg * 256 + n) = o;
                }
            }
        }
    }

    if (EPI == 0) {
        // fused scanA: per-chunk Horner carries from the staged u tile.
        // CTA = 128 t-contiguous rows (within one batch) = 2 chunks of 64.
        __syncthreads();
        const int s_loc = tid & 127;
        const int chl = tid >> 7;
        const int sg = nblock + s_loc;
        const float cc = g_coeff[sg];
        const float* col = su + chl * 64 * 128 + s_loc;
        float a = 0.0f;
        #pragma unroll 16
        for (int j = 0; j < 64; j++) a = fmaf(cc, a, col[j * 128]);
        const int b = (int)(mblock >> 12);
        const int chg = (int)((mblock & 4095) >> 6) + chl;
        g_carry[((size_t)b * NCH + chg) * SS + sg] = a;
    }
}

// ---------------- 3b. scan over chunks (also writes final_state) ----------------
__global__ void __launch_bounds__(256) scanB_kernel(const float* __restrict__ state0,
                                                    float* __restrict__ out) {
    int b = blockIdx.x, s = threadIdx.x;
    float cL = g_cL[s];
    float run = state0[b * SS + s];
    for (int ch = 0; ch < NCH; ch++) {
        size_t idx = ((size_t)b * NCH + ch) * SS + s;
        g_S0[idx] = run;
        run = fmaf(cL, run, g_carry[idx]);
    }
    out[(size_t)MM * HH + (size_t)b * SS + s] = run;
}

// ---------------- 3c. re-scan, write states as bf16 hi/lo cat ----------------
__global__ void __launch_bounds__(256) scanC_kernel() {
    int b = blockIdx.y, ch = blockIdx.x, s = threadIdx.x;
    float c = g_coeff[s];
    float run = g_S0[((size_t)b * NCH + ch) * SS + s];
    size_t row0 = (size_t)(b * TT + ch * LCH);
    #pragma unroll 4
    for (int j = 0; j < LCH; j++) {
        size_t row = row0 + j;
        run = fmaf(c, run, g_u[row * SS + s]);
        __nv_bfloat16 h = __float2bfloat16(run);
        g_st_cat[row * 512 + s] = h;
        g_st_cat[row * 512 + 256 + s] = __float2bfloat16(run - __bfloat162float(h));
    }
}

// ---------------- launch ----------------
extern "C" void kernel_launch(void* const* d_in, const int* in_sizes, int n_in,
                              void* d_out, int out_size) {
    const float* x       = (const float*)d_in[0];
    const float* state0  = (const float*)d_in[1];
    const float* its     = (const float*)d_in[2];
    const float* sth     = (const float*)d_in[3];
    const float* direct  = (const float*)d_in[4];
    const float* a_diag  = (const float*)d_in[5];
    const float* g_diag  = (const float*)d_in[6];
    const float* dt      = (const float*)d_in[7];
    const float* norm_w  = (const float*)d_in[8];
    const float* norm_b  = (const float*)d_in[9];
    const float* out_w   = (const float*)d_in[10];
    const float* out_b   = (const float*)d_in[11];
    float* out = (float*)d_out;

    __nv_bfloat16 *xncat, *stcat, *mixcat, *wcat;
    float* u;
    cudaGetSymbolAddress((void**)&xncat,  g_xn_cat);
    cudaGetSymbolAddress((void**)&stcat,  g_st_cat);
    cudaGetSymbolAddress((void**)&mixcat, g_mix_cat);
    cudaGetSymbolAddress((void**)&wcat,   g_wcat);
    cudaGetSymbolAddress((void**)&u,      g_u);

    cudaFuncSetAttribute(gemm_mma<0>, cudaFuncAttributeMaxDynamicSharedMemorySize, GSMEM);
    cudaFuncSetAttribute(gemm_mma<1>, cudaFuncAttributeMaxDynamicSharedMemorySize, GSMEM);
    cudaFuncSetAttribute(gemm_mma<2>, cudaFuncAttributeMaxDynamicSharedMemorySize, GSMEM);

    wsplit_kernel<<<dim3(256, 3), 256>>>(its, sth, out_w, a_diag, g_diag, dt);
    ln_kernel<<<MM / 8, 256>>>(x, norm_w, norm_b);

    dim3 ggrid(2, MM / 128);   // N/128, M/128
    gemm_mma<0><<<ggrid, 256, GSMEM>>>(xncat, wcat, u, nullptr, nullptr, nullptr, nullptr);

    scanB_kernel<<<BB, 256>>>(state0, out);
    scanC_kernel<<<dim3(NCH, BB), 256>>>();

    gemm_mma<1><<<ggrid, 256, GSMEM>>>(stcat, wcat + (size_t)1 * 256 * 768, nullptr, mixcat,
                                       direct, nullptr, xncat);
    gemm_mma<2><<<ggrid, 256, GSMEM>>>(mixcat, wcat + (size_t)2 * 256 * 768, out, nullptr,
                                       out_b, x, nullptr);
}

// round 7
// speedup vs baseline: 2.2911x; 1.0819x over previous
#include <cuda_runtime.h>
#include <cuda_bf16.h>
#include <cstdint>
#include <cstddef>

#define BB 32
#define TT 4096
#define HH 256
#define SS 256
#define MM (BB*TT)          // 131072 tokens
#define NCH 64              // chunks over T
#define LCH 64              // chunk length

// ---------------- scratch (static device globals; no allocations) ----------------
__device__ __nv_bfloat16 g_xn_cat[(size_t)MM*512];   // [hi | lo] layernormed x
__device__ __nv_bfloat16 g_st_cat[(size_t)MM*512];   // [hi | lo] states
__device__ __nv_bfloat16 g_mix_cat[(size_t)MM*512];  // [hi | lo] gelu(mixed)
__device__ float g_u[(size_t)MM*SS];                 // u (fp32, scan operand)
__device__ __nv_bfloat16 g_wcat[(size_t)3*256*512];  // per-weight [W_hi | W_lo]
__device__ float g_carry[(size_t)BB*NCH*SS];
__device__ float g_S0[(size_t)BB*NCH*SS];
__device__ float g_coeff[SS];
__device__ float g_cL[SS];

// ---------------- helpers ----------------
__device__ __forceinline__ uint32_t smem_u32(const void* p) {
    uint32_t a;
    asm("{ .reg .u64 t; cvta.to.shared.u64 t, %1; cvt.u32.u64 %0, t; }" : "=r"(a) : "l"(p));
    return a;
}
__device__ __forceinline__ float softplus_f(float x) {
    return fmaxf(x, 0.0f) + log1pf(expf(-fabsf(x)));
}
__device__ __forceinline__ float gelu_tanh(float x) {
    float x3 = x * x * x;
    float t = tanhf(0.7978845608028654f * (x + 0.044715f * x3));
    return 0.5f * x * (1.0f + t);
}
__device__ __forceinline__ unsigned pk2(float a, float b) {
    __nv_bfloat162 t = __floats2bfloat162_rn(a, b);
    return *reinterpret_cast<unsigned*>(&t);
}
__device__ __forceinline__ void unpk2(unsigned h, unsigned l, float& a, float& b) {
    a = __uint_as_float(h << 16) + __uint_as_float(l << 16);
    b = __uint_as_float(h & 0xffff0000u) + __uint_as_float(l & 0xffff0000u);
}

#define CP_ASYNC16(saddr, gptr) \
    asm volatile("cp.async.cg.shared.global [%0], [%1], 16;" :: "r"(saddr), "l"(gptr))
#define CP_COMMIT() asm volatile("cp.async.commit_group;" ::: "memory")
#define CP_WAIT(n)  asm volatile("cp.async.wait_group %0;" :: "n"(n) : "memory")
#define LDMATRIX_X4(r, addr) \
    asm volatile("ldmatrix.sync.aligned.m8n8.x4.shared.b16 {%0,%1,%2,%3}, [%4];" \
        : "=r"((r)[0]), "=r"((r)[1]), "=r"((r)[2]), "=r"((r)[3]) : "r"(addr))
#define MMA_BF16(d, a, b0, b1) \
    asm volatile("mma.sync.aligned.m16n8k16.row.col.f32.bf16.bf16.f32 " \
        "{%0,%1,%2,%3}, {%4,%5,%6,%7}, {%8,%9}, {%0,%1,%2,%3};" \
        : "+f"((d)[0]), "+f"((d)[1]), "+f"((d)[2]), "+f"((d)[3]) \
        : "r"((a)[0]), "r"((a)[1]), "r"((a)[2]), "r"((a)[3]), "r"(b0), "r"(b1))

// ---------------- 0. wsplit + coefficients (merged) ----------------
__global__ void wsplit_kernel(const float* __restrict__ its,
                              const float* __restrict__ sth,
                              const float* __restrict__ ow,
                              const float* __restrict__ a_diag,
                              const float* __restrict__ g_diag,
                              const float* __restrict__ dt) {
    int widx = blockIdx.y;
    int n = blockIdx.x;
    int k = threadIdx.x;
    if (widx == 0 && n == 0) {
        int s = k;
        float dt_s = softplus_f(dt[s]) + 1e-4f;
        float omega = a_diag[s] * dt_s;
        float decay = expf(-softplus_f(g_diag[s]) * dt_s);
        decay *= decay;
        float c = decay * cosf(omega);
        g_coeff[s] = c;
        float p = c;
        #pragma unroll
        for (int i = 0; i < 6; i++) p = p * p;
        g_cL[s] = p;
    }
    const float* W = (widx == 0) ? its : ((widx == 1) ? sth : ow);
    __nv_bfloat16* dst = g_wcat + (size_t)widx * 256 * 512;
    float v = W[n * 256 + k];
    __nv_bfloat16 h = __float2bfloat16(v);
    float lo = v - __bfloat162float(h);
    dst[(size_t)n * 512 + k] = h;
    dst[(size_t)n * 512 + 256 + k] = __float2bfloat16(lo);
}

// ---------------- 1. layernorm -> bf16 hi/lo cat ----------------
__global__ void __launch_bounds__(256) ln_kernel(const float* __restrict__ x,
                                                 const float* __restrict__ w,
                                                 const float* __restrict__ b) {
    int warp = threadIdx.x >> 5, lane = threadIdx.x & 31;
    size_t row = (size_t)blockIdx.x * 8 + warp;
    const float4* xr = reinterpret_cast<const float4*>(x + row * HH);
    float4 v0 = xr[lane];
    float4 v1 = xr[lane + 32];
    float sum = v0.x + v0.y + v0.z + v0.w + v1.x + v1.y + v1.z + v1.w;
    float sq  = v0.x*v0.x + v0.y*v0.y + v0.z*v0.z + v0.w*v0.w
              + v1.x*v1.x + v1.y*v1.y + v1.z*v1.z + v1.w*v1.w;
    #pragma unroll
    for (int o = 16; o > 0; o >>= 1) {
        sum += __shfl_xor_sync(0xffffffffu, sum, o);
        sq  += __shfl_xor_sync(0xffffffffu, sq,  o);
    }
    float mu = sum * (1.0f / HH);
    float var = sq * (1.0f / HH) - mu * mu;
    float rs = rsqrtf(var + 1e-5f);

    const float4* w4 = reinterpret_cast<const float4*>(w);
    const float4* b4 = reinterpret_cast<const float4*>(b);
    __nv_bfloat16* cat = g_xn_cat + row * 512;

    #pragma unroll
    for (int half = 0; half < 2; half++) {
        float4 v = half ? v1 : v0;
        int c0 = half * 128 + lane * 4;
        float4 wv = w4[half * 32 + lane], bv = b4[half * 32 + lane];
        float r0 = (v.x - mu) * rs * wv.x + bv.x;
        float r1 = (v.y - mu) * rs * wv.y + bv.y;
        float r2 = (v.z - mu) * rs * wv.z + bv.z;
        float r3 = (v.w - mu) * rs * wv.w + bv.w;
        __nv_bfloat16 h0 = __float2bfloat16(r0), h1 = __float2bfloat16(r1);
        __nv_bfloat16 h2 = __float2bfloat16(r2), h3 = __float2bfloat16(r3);
        uint2 hv;
        hv.x = pk2(r0, r1);
        hv.y = pk2(r2, r3);
        *reinterpret_cast<uint2*>(cat + c0) = hv;
        uint2 lv;
        lv.x = pk2(r0 - __bfloat162float(h0), r1 - __bfloat162float(h1));
        lv.y = pk2(r2 - __bfloat162float(h2), r3 - __bfloat162float(h3));
        *reinterpret_cast<uint2*>(cat + 256 + c0) = lv;
    }
}

// ---------------- 2. bf16x3 HMMA GEMM, dedup W loads, 3+3-slot pipeline ----------------
// A: [M,512] cat [A_hi|A_lo]. W: [256,512] cat [W_hi|W_lo].
// 12 steps, per k-range t (t=0..3, 64 cols each):
//   step 3t:   Ah_t x Wh_t    step 3t+1: Al_t x Wh_t    step 3t+2: Ah_t x Wl_t
// Loads: A 8 tiles (hi->slot t&1, lo->slot 2), W 8 tiles (hi->slot t&1, lo->slot 2).
// Slots verified conflict-free under the 2-ahead issue schedule.
// EPI 0: fp32 C + fused per-chunk scan carries. EPI 1: gelu(acc + d[n]*xn) -> cat.
// EPI 2: x + acc + out_b.
#define GSLOT 18432
#define GSMEM (6*GSLOT)
template <int EPI>
__global__ void __launch_bounds__(256, 2) gemm_mma(
    const __nv_bfloat16* __restrict__ A,
    const __nv_bfloat16* __restrict__ W,
    float* __restrict__ Cf,
    __nv_bfloat16* __restrict__ Cb,
    const float* __restrict__ auxf,
    const float* __restrict__ auxx,
    const __nv_bfloat16* __restrict__ xncat)
{
    extern __shared__ __nv_bfloat16 smem[];
    const uint32_t sbase = smem_u32(smem);
    const int tid = threadIdx.x;
    const int lane = tid & 31, wid = tid >> 5;
    const int wm = wid & 3, wn = wid >> 2;
    const size_t mblock = (size_t)blockIdx.y * 128;
    const int nblock = blockIdx.x * 128;

    // loader mapping: thread handles 4 (row,seg) pairs per tile
    const int lrow = tid >> 3;            // 0..31  (+32 per p)
    const int lseg = (tid & 7) * 8;
    const __nv_bfloat16* gA = A + (mblock + lrow) * 512 + lseg;
    const __nv_bfloat16* gW = W + (size_t)(nblock + lrow) * 512 + lseg;
    const uint32_t sAw = sbase + (lrow * 72 + lseg) * 2;
    const uint32_t sBw = sbase + 3*GSLOT + (lrow * 72 + lseg) * 2;

    // per-thread ldmatrix base offsets (within a slot)
    const uint32_t a_off = sbase + ((wm * 32 + (lane & 15)) * 72 + (lane >> 4) * 8) * 2;
    const uint32_t b_off = sbase + 3*GSLOT +
        ((wn * 64 + ((lane >> 3) & 1) * 8 + (lane & 7)) * 72 + (lane >> 4) * 8) * 2;

    float acc[2][8][4];
    #pragma unroll
    for (int i = 0; i < 2; i++)
        #pragma unroll
        for (int j = 0; j < 8; j++)
            #pragma unroll
            for (int q = 0; q < 4; q++) acc[i][j][q] = 0.0f;

    // issue loads needed by step s (s and derived values compile-time after unroll)
    auto issue_step = [&](int s) {
        const int t = s / 3, r = s % 3;
        if (r == 0) {        // new A hi t -> slot t&1 ; new W hi t -> slot t&1
            const uint32_t aso = (uint32_t)(t & 1) * GSLOT;
            #pragma unroll
            for (int p = 0; p < 4; p++)
                CP_ASYNC16(sAw + aso + p * 4608, gA + (size_t)p * 32 * 512 + t * 64);
            #pragma unroll
            for (int p = 0; p < 4; p++)
                CP_ASYNC16(sBw + aso + p * 4608, gW + (size_t)p * 32 * 512 + t * 64);
        } else if (r == 1) { // new A lo t -> slot 2
            #pragma unroll
            for (int p = 0; p < 4; p++)
                CP_ASYNC16(sAw + 2 * GSLOT + p * 4608,
                           gA + (size_t)p * 32 * 512 + 256 + t * 64);
        } else {             // new W lo t -> slot 2
            #pragma unroll
            for (int p = 0; p < 4; p++)
                CP_ASYNC16(sBw + 2 * GSLOT + p * 4608,
                           gW + (size_t)p * 32 * 512 + 256 + t * 64);
        }
        CP_COMMIT();
    };

    issue_step(0);
    issue_step(1);

    #pragma unroll
    for (int s = 0; s < 12; s++) {
        if (s < 11) { CP_WAIT(1); } else { CP_WAIT(0); }
        __syncthreads();
        if (s < 10) issue_step(s + 2);
        const int t = s / 3, r = s % 3;
        const uint32_t ab = a_off + (uint32_t)((r == 1) ? 2 : (t & 1)) * GSLOT;
        const uint32_t bb = b_off + (uint32_t)((r == 2) ? 2 : (t & 1)) * GSLOT;
        #pragma unroll
        for (int ks = 0; ks < 4; ks++) {
            uint32_t af[2][4];
            LDMATRIX_X4(af[0], ab + ks * 32);
            LDMATRIX_X4(af[1], ab + 2304 + ks * 32);     // +16 rows
            uint32_t bf[4][4];
            #pragma unroll
            for (int q = 0; q < 4; q++) LDMATRIX_X4(bf[q], bb + q * 2304 + ks * 32);
            #pragma unroll
            for (int mt = 0; mt < 2; mt++)
                #pragma unroll
                for (int nt = 0; nt < 8; nt++) {
                    const int q = nt >> 1, od = nt & 1;
                    MMA_BF16(acc[mt][nt], af[mt], bf[q][od], bf[q][2 + od]);
                }
        }
    }

    if (EPI == 0) __syncthreads();   // mainloop reads done before smem reuse
    float* su = reinterpret_cast<float*>(smem);   // [128][128] u tile (EPI 0)

    // ---- epilogue ----
    #pragma unroll
    for (int mt = 0; mt < 2; mt++) {
        #pragma unroll
        for (int h = 0; h < 2; h++) {
            const int ml = wm * 32 + mt * 16 + (lane >> 2) + h * 8;
            const size_t mg = mblock + ml;
            #pragma unroll
            for (int nt = 0; nt < 8; nt++) {
                const int nl = wn * 64 + nt * 8 + (lane & 3) * 2;
                const int n = nblock + nl;
                float v0 = acc[mt][nt][h * 2], v1 = acc[mt][nt][h * 2 + 1];
                if (EPI == 0) {
                    float2 o; o.x = v0; o.y = v1;
                    *reinterpret_cast<float2*>(Cf + mg * 256 + n) = o;
                    *reinterpret_cast<float2*>(su + ml * 128 + nl) = o;
                } else if (EPI == 1) {
                    uint32_t hv = *reinterpret_cast<const uint32_t*>(xncat + mg * 512 + n);
                    uint32_t lv = *reinterpret_cast<const uint32_t*>(xncat + mg * 512 + 256 + n);
                    float x0, x1; unpk2(hv, lv, x0, x1);
                    float2 dd = *reinterpret_cast<const float2*>(auxf + n);
                    float o0 = gelu_tanh(v0 + dd.x * x0);
                    float o1 = gelu_tanh(v1 + dd.y * x1);
                    __nv_bfloat16 h0 = __float2bfloat16(o0), h1 = __float2bfloat16(o1);
                    *reinterpret_cast<uint32_t*>(Cb + mg * 512 + n) = pk2(o0, o1);
                    *reinterpret_cast<uint32_t*>(Cb + mg * 512 + 256 + n) =
                        pk2(o0 - __bfloat162float(h0), o1 - __bfloat162float(h1));
                } else {
                    float2 xv = *reinterpret_cast<const float2*>(auxx + mg * 256 + n);
                    float2 bb2 = *reinterpret_cast<const float2*>(auxf + n);
                    float2 o;
                    o.x = xv.x + v0 + bb2.x;
                    o.y = xv.y + v1 + bb2.y;
                    *reinterpret_cast<float2*>(Cf + mg * 256 + n) = o;
                }
            }
        }
    }

    if (EPI == 0) {
        // fused scanA: per-chunk Horner carries from the staged u tile.
        __syncthreads();
        const int s_loc = tid & 127;
        const int chl = tid >> 7;
        const int sg = nblock + s_loc;
        const float cc = g_coeff[sg];
        const float* col = su + chl * 64 * 128 + s_loc;
        float a = 0.0f;
        #pragma unroll 16
        for (int j = 0; j < 64; j++) a = fmaf(cc, a, col[j * 128]);
        const int b = (int)(mblock >> 12);
        const int chg = (int)((mblock & 4095) >> 6) + chl;
        g_carry[((size_t)b * NCH + chg) * SS + sg] = a;
    }
}

// ---------------- 3b. chunk-level scan (latency-optimized: prefetch all carries) ----
__global__ void __launch_bounds__(256) scanB_kernel(const float* __restrict__ state0,
                                                    float* __restrict__ out) {
    int b = blockIdx.x, s = threadIdx.x;
    const float* cp = g_carry + (size_t)b * NCH * SS + s;
    float carr[NCH];
    #pragma unroll
    for (int ch = 0; ch < NCH; ch++) carr[ch] = cp[(size_t)ch * SS];   // 64 parallel loads
    float cL = g_cL[s];
    float run = state0[b * SS + s];
    float* s0 = g_S0 + (size_t)b * NCH * SS + s;
    #pragma unroll
    for (int ch = 0; ch < NCH; ch++) {
        s0[(size_t)ch * SS] = run;
        run = fmaf(cL, run, carr[ch]);
    }
    out[(size_t)MM * HH + (size_t)b * SS + s] = run;
}

// ---------------- 3c. re-scan, write states as bf16 hi/lo cat ----------------
__global__ void __launch_bounds__(256) scanC_kernel() {
    int b = blockIdx.y, ch = blockIdx.x, s = threadIdx.x;
    float c = g_coeff[s];
    float run = g_S0[((size_t)b * NCH + ch) * SS + s];
    size_t row0 = (size_t)(b * TT + ch * LCH);
    #pragma unroll 4
    for (int j = 0; j < LCH; j++) {
        size_t row = row0 + j;
        run = fmaf(c, run, g_u[row * SS + s]);
        __nv_bfloat16 h = __float2bfloat16(run);
        g_st_cat[row * 512 + s] = h;
        g_st_cat[row * 512 + 256 + s] = __float2bfloat16(run - __bfloat162float(h));
    }
}

// ---------------- launch ----------------
extern "C" void kernel_launch(void* const* d_in, const int* in_sizes, int n_in,
                              void* d_out, int out_size) {
    const float* x       = (const float*)d_in[0];
    const float* state0  = (const float*)d_in[1];
    const float* its     = (const float*)d_in[2];
    const float* sth     = (const float*)d_in[3];
    const float* direct  = (const float*)d_in[4];
    const float* a_diag  = (const float*)d_in[5];
    const float* g_diag  = (const float*)d_in[6];
    const float* dt      = (const float*)d_in[7];
    const float* norm_w  = (const float*)d_in[8];
    const float* norm_b  = (const float*)d_in[9];
    const float* out_w   = (const float*)d_in[10];
    const float* out_b   = (const float*)d_in[11];
    float* out = (float*)d_out;

    __nv_bfloat16 *xncat, *stcat, *mixcat, *wcat;
    float* u;
    cudaGetSymbolAddress((void**)&xncat,  g_xn_cat);
    cudaGetSymbolAddress((void**)&stcat,  g_st_cat);
    cudaGetSymbolAddress((void**)&mixcat, g_mix_cat);
    cudaGetSymbolAddress((void**)&wcat,   g_wcat);
    cudaGetSymbolAddress((void**)&u,      g_u);

    cudaFuncSetAttribute(gemm_mma<0>, cudaFuncAttributeMaxDynamicSharedMemorySize, GSMEM);
    cudaFuncSetAttribute(gemm_mma<1>, cudaFuncAttributeMaxDynamicSharedMemorySize, GSMEM);
    cudaFuncSetAttribute(gemm_mma<2>, cudaFuncAttributeMaxDynamicSharedMemorySize, GSMEM);

    wsplit_kernel<<<dim3(256, 3), 256>>>(its, sth, out_w, a_diag, g_diag, dt);
    ln_kernel<<<MM / 8, 256>>>(x, norm_w, norm_b);

    dim3 ggrid(2, MM / 128);   // N/128, M/128
    gemm_mma<0><<<ggrid, 256, GSMEM>>>(xncat, wcat, u, nullptr, nullptr, nullptr, nullptr);

    scanB_kernel<<<BB, 256>>>(state0, out);
    scanC_kernel<<<dim3(NCH, BB), 256>>>();

    gemm_mma<1><<<ggrid, 256, GSMEM>>>(stcat, wcat + (size_t)1 * 256 * 512, nullptr, mixcat,
                                       direct, nullptr, xncat);
    gemm_mma<2><<<ggrid, 256, GSMEM>>>(mixcat, wcat + (size_t)2 * 256 * 512, out, nullptr,
                                       out_b, x, nullptr);
}

// round 8
// speedup vs baseline: 2.8842x; 1.2589x over previous
#include <cuda_runtime.h>
#include <cuda_fp16.h>
#include <cstdint>
#include <cstddef>

#define BB 32
#define TT 4096
#define HH 256
#define SS 256
#define MM (BB*TT)          // 131072 tokens
#define NCH 64              // chunks over T
#define LCH 64              // chunk length

// ---------------- scratch (static device globals; no allocations) ----------------
__device__ __half g_xn_cat[(size_t)MM*512];   // [hi | lo] layernormed x (fp16)
__device__ __half g_st_cat[(size_t)MM*512];   // [hi | lo] states
__device__ __half g_mix_cat[(size_t)MM*512];  // [hi | lo] gelu(mixed)
__device__ float g_u[(size_t)MM*SS];          // u (fp32, scan operand)
__device__ __half g_wcat[(size_t)3*256*256];  // per-weight W_hi (fp16)
__device__ float g_carry[(size_t)BB*NCH*SS];
__device__ float g_S0[(size_t)BB*NCH*SS];
__device__ float g_coeff[SS];
__device__ float g_cL[SS];

// ---------------- helpers ----------------
__device__ __forceinline__ uint32_t smem_u32(const void* p) {
    uint32_t a;
    asm("{ .reg .u64 t; cvta.to.shared.u64 t, %1; cvt.u32.u64 %0, t; }" : "=r"(a) : "l"(p));
    return a;
}
__device__ __forceinline__ float softplus_f(float x) {
    return fmaxf(x, 0.0f) + log1pf(expf(-fabsf(x)));
}
__device__ __forceinline__ float gelu_tanh(float x) {
    float x3 = x * x * x;
    float t = tanhf(0.7978845608028654f * (x + 0.044715f * x3));
    return 0.5f * x * (1.0f + t);
}
__device__ __forceinline__ unsigned pk2h(float a, float b) {
    __half2 t = __floats2half2_rn(a, b);
    return *reinterpret_cast<unsigned*>(&t);
}
__device__ __forceinline__ void unpk2h(unsigned h, unsigned l, float& a, float& b) {
    __half2 hh = *reinterpret_cast<__half2*>(&h);
    __half2 ll = *reinterpret_cast<__half2*>(&l);
    a = __half2float(__low2half(hh)) + __half2float(__low2half(ll));
    b = __half2float(__high2half(hh)) + __half2float(__high2half(ll));
}

#define CP_ASYNC16(saddr, gptr) \
    asm volatile("cp.async.cg.shared.global [%0], [%1], 16;" :: "r"(saddr), "l"(gptr))
#define CP_COMMIT() asm volatile("cp.async.commit_group;" ::: "memory")
#define CP_WAIT(n)  asm volatile("cp.async.wait_group %0;" :: "n"(n) : "memory")
#define LDMATRIX_X4(r, addr) \
    asm volatile("ldmatrix.sync.aligned.m8n8.x4.shared.b16 {%0,%1,%2,%3}, [%4];" \
        : "=r"((r)[0]), "=r"((r)[1]), "=r"((r)[2]), "=r"((r)[3]) : "r"(addr))
#define MMA_F16(d, a, b0, b1) \
    asm volatile("mma.sync.aligned.m16n8k16.row.col.f32.f16.f16.f32 " \
        "{%0,%1,%2,%3}, {%4,%5,%6,%7}, {%8,%9}, {%0,%1,%2,%3};" \
        : "+f"((d)[0]), "+f"((d)[1]), "+f"((d)[2]), "+f"((d)[3]) \
        : "r"((a)[0]), "r"((a)[1]), "r"((a)[2]), "r"((a)[3]), "r"(b0), "r"(b1))

// ---------------- 0. wsplit (fp16 hi only) + coefficients ----------------
__global__ void wsplit_kernel(const float* __restrict__ its,
                              const float* __restrict__ sth,
                              const float* __restrict__ ow,
                              const float* __restrict__ a_diag,
                              const float* __restrict__ g_diag,
                              const float* __restrict__ dt) {
    int widx = blockIdx.y;
    int n = blockIdx.x;
    int k = threadIdx.x;
    if (widx == 0 && n == 0) {
        int s = k;
        float dt_s = softplus_f(dt[s]) + 1e-4f;
        float omega = a_diag[s] * dt_s;
        float decay = expf(-softplus_f(g_diag[s]) * dt_s);
        decay *= decay;
        float c = decay * cosf(omega);
        g_coeff[s] = c;
        float p = c;
        #pragma unroll
        for (int i = 0; i < 6; i++) p = p * p;
        g_cL[s] = p;
    }
    const float* W = (widx == 0) ? its : ((widx == 1) ? sth : ow);
    g_wcat[(size_t)widx * 256 * 256 + (size_t)n * 256 + k] = __float2half_rn(W[n * 256 + k]);
}

// ---------------- 1. layernorm -> fp16 hi/lo cat ----------------
__global__ void __launch_bounds__(256) ln_kernel(const float* __restrict__ x,
                                                 const float* __restrict__ w,
                                                 const float* __restrict__ b) {
    int warp = threadIdx.x >> 5, lane = threadIdx.x & 31;
    size_t row = (size_t)blockIdx.x * 8 + warp;
    const float4* xr = reinterpret_cast<const float4*>(x + row * HH);
    float4 v0 = xr[lane];
    float4 v1 = xr[lane + 32];
    float sum = v0.x + v0.y + v0.z + v0.w + v1.x + v1.y + v1.z + v1.w;
    float sq  = v0.x*v0.x + v0.y*v0.y + v0.z*v0.z + v0.w*v0.w
              + v1.x*v1.x + v1.y*v1.y + v1.z*v1.z + v1.w*v1.w;
    #pragma unroll
    for (int o = 16; o > 0; o >>= 1) {
        sum += __shfl_xor_sync(0xffffffffu, sum, o);
        sq  += __shfl_xor_sync(0xffffffffu, sq,  o);
    }
    float mu = sum * (1.0f / HH);
    float var = sq * (1.0f / HH) - mu * mu;
    float rs = rsqrtf(var + 1e-5f);

    const float4* w4 = reinterpret_cast<const float4*>(w);
    const float4* b4 = reinterpret_cast<const float4*>(b);
    __half* cat = g_xn_cat + row * 512;

    #pragma unroll
    for (int half_ = 0; half_ < 2; half_++) {
        float4 v = half_ ? v1 : v0;
        int c0 = half_ * 128 + lane * 4;
        float4 wv = w4[half_ * 32 + lane], bv = b4[half_ * 32 + lane];
        float r0 = (v.x - mu) * rs * wv.x + bv.x;
        float r1 = (v.y - mu) * rs * wv.y + bv.y;
        float r2 = (v.z - mu) * rs * wv.z + bv.z;
        float r3 = (v.w - mu) * rs * wv.w + bv.w;
        __half h0 = __float2half_rn(r0), h1 = __float2half_rn(r1);
        __half h2 = __float2half_rn(r2), h3 = __float2half_rn(r3);
        uint2 hv;
        hv.x = pk2h(r0, r1);
        hv.y = pk2h(r2, r3);
        *reinterpret_cast<uint2*>(cat + c0) = hv;
        uint2 lv;
        lv.x = pk2h(r0 - __half2float(h0), r1 - __half2float(h1));
        lv.y = pk2h(r2 - __half2float(h2), r3 - __half2float(h3));
        *reinterpret_cast<uint2*>(cat + 256 + c0) = lv;
    }
}

// ---------------- 2. fp16x2 HMMA GEMM: C = (Ah+Al) x Wh, 8 steps ----------------
// A: [M,512] cat [Ah|Al] fp16. W: [256,256] Wh fp16.
// Step s: t = s>>1 (k-range, 64 cols), r = s&1 (hi/lo). A col = r*256 + t*64.
// Slots: A -> s%3 (3 slots), W_t -> t&1 (2 slots, loaded only at r==0, reused r==1).
// SMEM: 5 slots x 18432 B = 92160 B. 2 CTAs/SM.
// EPI 0: fp32 C + fused per-chunk scan carries. EPI 1: gelu(acc + d[n]*xn) -> fp16 cat.
// EPI 2: x + acc + out_b.
#define GSLOT 18432
#define GSMEM (5*GSLOT)
template <int EPI>
__global__ void __launch_bounds__(256, 2) gemm_mma(
    const __half* __restrict__ A,
    const __half* __restrict__ W,
    float* __restrict__ Cf,
    __half* __restrict__ Cb,
    const float* __restrict__ auxf,
    const float* __restrict__ auxx,
    const __half* __restrict__ xncat)
{
    extern __shared__ __half smem[];
    const uint32_t sbase = smem_u32(smem);
    const int tid = threadIdx.x;
    const int lane = tid & 31, wid = tid >> 5;
    const int wm = wid & 3, wn = wid >> 2;
    const size_t mblock = (size_t)blockIdx.y * 128;
    const int nblock = blockIdx.x * 128;

    // loader mapping: thread handles 4 (row,seg) pairs per tile
    const int lrow = tid >> 3;            // 0..31  (+32 per p)
    const int lseg = (tid & 7) * 8;
    const __half* gA = A + (mblock + lrow) * 512 + lseg;
    const __half* gW = W + (size_t)(nblock + lrow) * 256 + lseg;
    const uint32_t sAw = sbase + (lrow * 72 + lseg) * 2;
    const uint32_t sBw = sbase + 3*GSLOT + (lrow * 72 + lseg) * 2;

    // per-thread ldmatrix base offsets (within a slot)
    const uint32_t a_off = sbase + ((wm * 32 + (lane & 15)) * 72 + (lane >> 4) * 8) * 2;
    const uint32_t b_off = sbase + 3*GSLOT +
        ((wn * 64 + ((lane >> 3) & 1) * 8 + (lane & 7)) * 72 + (lane >> 4) * 8) * 2;

    float acc[2][8][4];
    #pragma unroll
    for (int i = 0; i < 2; i++)
        #pragma unroll
        for (int j = 0; j < 8; j++)
            #pragma unroll
            for (int q = 0; q < 4; q++) acc[i][j][q] = 0.0f;

    // issue loads for step s (compile-time after unroll)
    auto issue_step = [&](int s) {
        const int t = s >> 1, r = s & 1;
        const uint32_t aso = (uint32_t)(s % 3) * GSLOT;
        const int acol = r * 256 + t * 64;
        #pragma unroll
        for (int p = 0; p < 4; p++)
            CP_ASYNC16(sAw + aso + p * 4608, gA + (size_t)p * 32 * 512 + acol);
        if (r == 0) {
            const uint32_t wso = (uint32_t)(t & 1) * GSLOT;
            #pragma unroll
            for (int p = 0; p < 4; p++)
                CP_ASYNC16(sBw + wso + p * 4608, gW + (size_t)p * 32 * 256 + t * 64);
        }
        CP_COMMIT();
    };

    issue_step(0);
    issue_step(1);

    #pragma unroll
    for (int s = 0; s < 8; s++) {
        if (s < 7) { CP_WAIT(1); } else { CP_WAIT(0); }
        __syncthreads();
        if (s < 6) issue_step(s + 2);
        const int t = s >> 1;
        const uint32_t ab = a_off + (uint32_t)(s % 3) * GSLOT;
        const uint32_t bb = b_off + (uint32_t)(t & 1) * GSLOT;
        #pragma unroll
        for (int ks = 0; ks < 4; ks++) {
            uint32_t af[2][4];
            LDMATRIX_X4(af[0], ab + ks * 32);
            LDMATRIX_X4(af[1], ab + 2304 + ks * 32);     // +16 rows
            uint32_t bf[4][4];
            #pragma unroll
            for (int q = 0; q < 4; q++) LDMATRIX_X4(bf[q], bb + q * 2304 + ks * 32);
            #pragma unroll
            for (int mt = 0; mt < 2; mt++)
                #pragma unroll
                for (int nt = 0; nt < 8; nt++) {
                    const int q = nt >> 1, od = nt & 1;
                    MMA_F16(acc[mt][nt], af[mt], bf[q][od], bf[q][2 + od]);
                }
        }
    }

    if (EPI == 0) __syncthreads();   // mainloop reads done before smem reuse
    float* su = reinterpret_cast<float*>(smem);   // [128][128] u tile (EPI 0)

    // ---- epilogue ----
    #pragma unroll
    for (int mt = 0; mt < 2; mt++) {
        #pragma unroll
        for (int h = 0; h < 2; h++) {
            const int ml = wm * 32 + mt * 16 + (lane >> 2) + h * 8;
            const size_t mg = mblock + ml;
            #pragma unroll
            for (int nt = 0; nt < 8; nt++) {
                const int nl = wn * 64 + nt * 8 + (lane & 3) * 2;
                const int n = nblock + nl;
                float v0 = acc[mt][nt][h * 2], v1 = acc[mt][nt][h * 2 + 1];
                if (EPI == 0) {
                    float2 o; o.x = v0; o.y = v1;
                    *reinterpret_cast<float2*>(Cf + mg * 256 + n) = o;
                    *reinterpret_cast<float2*>(su + ml * 128 + nl) = o;
                } else if (EPI == 1) {
                    uint32_t hv = *reinterpret_cast<const uint32_t*>(xncat + mg * 512 + n);
                    uint32_t lv = *reinterpret_cast<const uint32_t*>(xncat + mg * 512 + 256 + n);
                    float x0, x1; unpk2h(hv, lv, x0, x1);
                    float2 dd = *reinterpret_cast<const float2*>(auxf + n);
                    float o0 = gelu_tanh(v0 + dd.x * x0);
                    float o1 = gelu_tanh(v1 + dd.y * x1);
                    __half h0 = __float2half_rn(o0), h1 = __float2half_rn(o1);
                    *reinterpret_cast<uint32_t*>(Cb + mg * 512 + n) = pk2h(o0, o1);
                    *reinterpret_cast<uint32_t*>(Cb + mg * 512 + 256 + n) =
                        pk2h(o0 - __half2float(h0), o1 - __half2float(h1));
                } else {
                    float2 xv = *reinterpret_cast<const float2*>(auxx + mg * 256 + n);
                    float2 bb2 = *reinterpret_cast<const float2*>(auxf + n);
                    float2 o;
                    o.x = xv.x + v0 + bb2.x;
                    o.y = xv.y + v1 + bb2.y;
                    *reinterpret_cast<float2*>(Cf + mg * 256 + n) = o;
                }
            }
        }
    }

    if (EPI == 0) {
        // fused scanA: per-chunk Horner carries from the staged u tile.
        __syncthreads();
        const int s_loc = tid & 127;
        const int chl = tid >> 7;
        const int sg = nblock + s_loc;
        const float cc = g_coeff[sg];
        const float* col = su + chl * 64 * 128 + s_loc;
        float a = 0.0f;
        #pragma unroll 16
        for (int j = 0; j < 64; j++) a = fmaf(cc, a, col[j * 128]);
        const int b = (int)(mblock >> 12);
        const int chg = (int)((mblock & 4095) >> 6) + chl;
        g_carry[((size_t)b * NCH + chg) * SS + sg] = a;
    }
}

// ---------------- 3b. chunk-level scan (prefetch all carries) ----------------
__global__ void __launch_bounds__(256) scanB_kernel(const float* __restrict__ state0,
                                                    float* __restrict__ out) {
    int b = blockIdx.x, s = threadIdx.x;
    const float* cp = g_carry + (size_t)b * NCH * SS + s;
    float carr[NCH];
    #pragma unroll
    for (int ch = 0; ch < NCH; ch++) carr[ch] = cp[(size_t)ch * SS];
    float cL = g_cL[s];
    float run = state0[b * SS + s];
    float* s0 = g_S0 + (size_t)b * NCH * SS + s;
    #pragma unroll
    for (int ch = 0; ch < NCH; ch++) {
        s0[(size_t)ch * SS] = run;
        run = fmaf(cL, run, carr[ch]);
    }
    out[(size_t)MM * HH + (size_t)b * SS + s] = run;
}

// ---------------- 3c. re-scan, write states as fp16 hi/lo cat ----------------
__global__ void __launch_bounds__(256) scanC_kernel() {
    int b = blockIdx.y, ch = blockIdx.x, s = threadIdx.x;
    float c = g_coeff[s];
    float run = g_S0[((size_t)b * NCH + ch) * SS + s];
    size_t row0 = (size_t)(b * TT + ch * LCH);
    #pragma unroll 4
    for (int j = 0; j < LCH; j++) {
        size_t row = row0 + j;
        run = fmaf(c, run, g_u[row * SS + s]);
        __half h = __float2half_rn(run);
        g_st_cat[row * 512 + s] = h;
        g_st_cat[row * 512 + 256 + s] = __float2half_rn(run - __half2float(h));
    }
}

// ---------------- launch ----------------
extern "C" void kernel_launch(void* const* d_in, const int* in_sizes, int n_in,
                              void* d_out, int out_size) {
    const float* x       = (const float*)d_in[0];
    const float* state0  = (const float*)d_in[1];
    const float* its     = (const float*)d_in[2];
    const float* sth     = (const float*)d_in[3];
    const float* direct  = (const float*)d_in[4];
    const float* a_diag  = (const float*)d_in[5];
    const float* g_diag  = (const float*)d_in[6];
    const float* dt      = (const float*)d_in[7];
    const float* norm_w  = (const float*)d_in[8];
    const float* norm_b  = (const float*)d_in[9];
    const float* out_w   = (const float*)d_in[10];
    const float* out_b   = (const float*)d_in[11];
    float* out = (float*)d_out;

    __half *xncat, *stcat, *mixcat, *wcat;
    float* u;
    cudaGetSymbolAddress((void**)&xncat,  g_xn_cat);
    cudaGetSymbolAddress((void**)&stcat,  g_st_cat);
    cudaGetSymbolAddress((void**)&mixcat, g_mix_cat);
    cudaGetSymbolAddress((void**)&wcat,   g_wcat);
    cudaGetSymbolAddress((void**)&u,      g_u);

    cudaFuncSetAttribute(gemm_mma<0>, cudaFuncAttributeMaxDynamicSharedMemorySize, GSMEM);
    cudaFuncSetAttribute(gemm_mma<1>, cudaFuncAttributeMaxDynamicSharedMemorySize, GSMEM);
    cudaFuncSetAttribute(gemm_mma<2>, cudaFuncAttributeMaxDynamicSharedMemorySize, GSMEM);

    wsplit_kernel<<<dim3(256, 3), 256>>>(its, sth, out_w, a_diag, g_diag, dt);
    ln_kernel<<<MM / 8, 256>>>(x, norm_w, norm_b);

    dim3 ggrid(2, MM / 128);   // N/128, M/128
    gemm_mma<0><<<ggrid, 256, GSMEM>>>(xncat, wcat, u, nullptr, nullptr, nullptr, nullptr);

    scanB_kernel<<<BB, 256>>>(state0, out);
    scanC_kernel<<<dim3(NCH, BB), 256>>>();

    gemm_mma<1><<<ggrid, 256, GSMEM>>>(stcat, wcat + (size_t)1 * 256 * 256, nullptr, mixcat,
                                       direct, nullptr, xncat);
    gemm_mma<2><<<ggrid, 256, GSMEM>>>(mixcat, wcat + (size_t)2 * 256 * 256, out, nullptr,
                                       out_b, x, nullptr);
}

// round 9
// speedup vs baseline: 3.8752x; 1.3436x over previous
#include <cuda_runtime.h>
#include <cuda_fp16.h>
#include <cstdint>
#include <cstddef>

#define BB 32
#define TT 4096
#define HH 256
#define SS 256
#define MM (BB*TT)          // 131072 tokens
#define NCH 64              // chunks over T
#define LCH 64              // chunk length

// ---------------- scratch (static device globals; no allocations) ----------------
__device__ __half g_xn[(size_t)MM*256];       // layernormed x (fp16)
__device__ __half g_st[(size_t)MM*256];       // states (fp16)
__device__ __half g_mix[(size_t)MM*256];      // gelu(mixed) (fp16)
__device__ float g_u[(size_t)MM*SS];          // u (fp32, scan operand)
__device__ __half g_wcat[(size_t)3*256*256];  // per-weight W (fp16)
__device__ float g_carry[(size_t)BB*NCH*SS];
__device__ float g_S0[(size_t)BB*NCH*SS];
__device__ float g_coeff[SS];
__device__ float g_cL[SS];

// ---------------- helpers ----------------
__device__ __forceinline__ uint32_t smem_u32(const void* p) {
    uint32_t a;
    asm("{ .reg .u64 t; cvta.to.shared.u64 t, %1; cvt.u32.u64 %0, t; }" : "=r"(a) : "l"(p));
    return a;
}
__device__ __forceinline__ float softplus_f(float x) {
    return fmaxf(x, 0.0f) + log1pf(expf(-fabsf(x)));
}
__device__ __forceinline__ float gelu_tanh(float x) {
    float x3 = x * x * x;
    float t = tanhf(0.7978845608028654f * (x + 0.044715f * x3));
    return 0.5f * x * (1.0f + t);
}
__device__ __forceinline__ unsigned pk2h(float a, float b) {
    __half2 t = __floats2half2_rn(a, b);
    return *reinterpret_cast<unsigned*>(&t);
}

#define CP_ASYNC16(saddr, gptr) \
    asm volatile("cp.async.cg.shared.global [%0], [%1], 16;" :: "r"(saddr), "l"(gptr))
#define CP_COMMIT() asm volatile("cp.async.commit_group;" ::: "memory")
#define CP_WAIT(n)  asm volatile("cp.async.wait_group %0;" :: "n"(n) : "memory")
#define LDMATRIX_X4(r, addr) \
    asm volatile("ldmatrix.sync.aligned.m8n8.x4.shared.b16 {%0,%1,%2,%3}, [%4];" \
        : "=r"((r)[0]), "=r"((r)[1]), "=r"((r)[2]), "=r"((r)[3]) : "r"(addr))
#define MMA_F16(d, a, b0, b1) \
    asm volatile("mma.sync.aligned.m16n8k16.row.col.f32.f16.f16.f32 " \
        "{%0,%1,%2,%3}, {%4,%5,%6,%7}, {%8,%9}, {%0,%1,%2,%3};" \
        : "+f"((d)[0]), "+f"((d)[1]), "+f"((d)[2]), "+f"((d)[3]) \
        : "r"((a)[0]), "r"((a)[1]), "r"((a)[2]), "r"((a)[3]), "r"(b0), "r"(b1))

// ---------------- 0. wsplit (fp16) + coefficients ----------------
__global__ void wsplit_kernel(const float* __restrict__ its,
                              const float* __restrict__ sth,
                              const float* __restrict__ ow,
                              const float* __restrict__ a_diag,
                              const float* __restrict__ g_diag,
                              const float* __restrict__ dt) {
    int widx = blockIdx.y;
    int n = blockIdx.x;
    int k = threadIdx.x;
    if (widx == 0 && n == 0) {
        int s = k;
        float dt_s = softplus_f(dt[s]) + 1e-4f;
        float omega = a_diag[s] * dt_s;
        float decay = expf(-softplus_f(g_diag[s]) * dt_s);
        decay *= decay;
        float c = decay * cosf(omega);
        g_coeff[s] = c;
        float p = c;
        #pragma unroll
        for (int i = 0; i < 6; i++) p = p * p;
        g_cL[s] = p;
    }
    const float* W = (widx == 0) ? its : ((widx == 1) ? sth : ow);
    g_wcat[(size_t)widx * 256 * 256 + (size_t)n * 256 + k] = __float2half_rn(W[n * 256 + k]);
}

// ---------------- 1. layernorm -> fp16 ----------------
__global__ void __launch_bounds__(256) ln_kernel(const float* __restrict__ x,
                                                 const float* __restrict__ w,
                                                 const float* __restrict__ b) {
    int warp = threadIdx.x >> 5, lane = threadIdx.x & 31;
    size_t row = (size_t)blockIdx.x * 8 + warp;
    const float4* xr = reinterpret_cast<const float4*>(x + row * HH);
    float4 v0 = xr[lane];
    float4 v1 = xr[lane + 32];
    float sum = v0.x + v0.y + v0.z + v0.w + v1.x + v1.y + v1.z + v1.w;
    float sq  = v0.x*v0.x + v0.y*v0.y + v0.z*v0.z + v0.w*v0.w
              + v1.x*v1.x + v1.y*v1.y + v1.z*v1.z + v1.w*v1.w;
    #pragma unroll
    for (int o = 16; o > 0; o >>= 1) {
        sum += __shfl_xor_sync(0xffffffffu, sum, o);
        sq  += __shfl_xor_sync(0xffffffffu, sq,  o);
    }
    float mu = sum * (1.0f / HH);
    float var = sq * (1.0f / HH) - mu * mu;
    float rs = rsqrtf(var + 1e-5f);

    const float4* w4 = reinterpret_cast<const float4*>(w);
    const float4* b4 = reinterpret_cast<const float4*>(b);
    __half* dst = g_xn + row * 256;

    #pragma unroll
    for (int half_ = 0; half_ < 2; half_++) {
        float4 v = half_ ? v1 : v0;
        int c0 = half_ * 128 + lane * 4;
        float4 wv = w4[half_ * 32 + lane], bv = b4[half_ * 32 + lane];
        float r0 = (v.x - mu) * rs * wv.x + bv.x;
        float r1 = (v.y - mu) * rs * wv.y + bv.y;
        float r2 = (v.z - mu) * rs * wv.z + bv.z;
        float r3 = (v.w - mu) * rs * wv.w + bv.w;
        uint2 hv;
        hv.x = pk2h(r0, r1);
        hv.y = pk2h(r2, r3);
        *reinterpret_cast<uint2*>(dst + c0) = hv;
    }
}

// ---------------- 2. fp16 HMMA GEMM: C = A x W, K=256, 4 steps ----------------
// A: [M,256] fp16. W: [256,256] fp16 (row n = output col, K contiguous).
// Step s (0..3): cols s*64. Slots: A -> s%3 (slots 0-2), W -> s%3 (slots 3-5).
// SMEM: 6 slots x 18432 B = 110592 B. 2 CTAs/SM.
// EPI 0: fp32 C + fused per-chunk scan carries. EPI 1: gelu(acc + d[n]*xn) -> fp16.
// EPI 2: x + acc + out_b (fp32 out).
#define GSLOT 18432
#define GSMEM (6*GSLOT)
template <int EPI>
__global__ void __launch_bounds__(256, 2) gemm_mma(
    const __half* __restrict__ A,
    const __half* __restrict__ W,
    float* __restrict__ Cf,
    __half* __restrict__ Cb,
    const float* __restrict__ auxf,
    const float* __restrict__ auxx,
    const __half* __restrict__ xn)
{
    extern __shared__ __half smem[];
    const uint32_t sbase = smem_u32(smem);
    const int tid = threadIdx.x;
    const int lane = tid & 31, wid = tid >> 5;
    const int wm = wid & 3, wn = wid >> 2;
    const size_t mblock = (size_t)blockIdx.y * 128;
    const int nblock = blockIdx.x * 128;

    // loader mapping: thread handles 4 (row,seg) pairs per tile
    const int lrow = tid >> 3;            // 0..31  (+32 per p)
    const int lseg = (tid & 7) * 8;
    const __half* gA = A + (mblock + lrow) * 256 + lseg;
    const __half* gW = W + (size_t)(nblock + lrow) * 256 + lseg;
    const uint32_t sAw = sbase + (lrow * 72 + lseg) * 2;
    const uint32_t sBw = sbase + 3*GSLOT + (lrow * 72 + lseg) * 2;

    // per-thread ldmatrix base offsets (within a slot)
    const uint32_t a_off = sbase + ((wm * 32 + (lane & 15)) * 72 + (lane >> 4) * 8) * 2;
    const uint32_t b_off = sbase + 3*GSLOT +
        ((wn * 64 + ((lane >> 3) & 1) * 8 + (lane & 7)) * 72 + (lane >> 4) * 8) * 2;

    float acc[2][8][4];
    #pragma unroll
    for (int i = 0; i < 2; i++)
        #pragma unroll
        for (int j = 0; j < 8; j++)
            #pragma unroll
            for (int q = 0; q < 4; q++) acc[i][j][q] = 0.0f;

    auto issue_step = [&](int s) {
        const uint32_t so = (uint32_t)(s % 3) * GSLOT;
        const int col = s * 64;
        #pragma unroll
        for (int p = 0; p < 4; p++)
            CP_ASYNC16(sAw + so + p * 4608, gA + (size_t)p * 32 * 256 + col);
        #pragma unroll
        for (int p = 0; p < 4; p++)
            CP_ASYNC16(sBw + so + p * 4608, gW + (size_t)p * 32 * 256 + col);
        CP_COMMIT();
    };

    issue_step(0);
    issue_step(1);

    #pragma unroll
    for (int s = 0; s < 4; s++) {
        if (s < 3) { CP_WAIT(1); } else { CP_WAIT(0); }
        __syncthreads();
        if (s < 2) issue_step(s + 2);
        const uint32_t ab = a_off + (uint32_t)(s % 3) * GSLOT;
        const uint32_t bb = b_off + (uint32_t)(s % 3) * GSLOT;
        #pragma unroll
        for (int ks = 0; ks < 4; ks++) {
            uint32_t af[2][4];
            LDMATRIX_X4(af[0], ab + ks * 32);
            LDMATRIX_X4(af[1], ab + 2304 + ks * 32);     // +16 rows
            uint32_t bf[4][4];
            #pragma unroll
            for (int q = 0; q < 4; q++) LDMATRIX_X4(bf[q], bb + q * 2304 + ks * 32);
            #pragma unroll
            for (int mt = 0; mt < 2; mt++)
                #pragma unroll
                for (int nt = 0; nt < 8; nt++) {
                    const int q = nt >> 1, od = nt & 1;
                    MMA_F16(acc[mt][nt], af[mt], bf[q][od], bf[q][2 + od]);
                }
        }
    }

    if (EPI == 0) __syncthreads();   // mainloop reads done before smem reuse
    float* su = reinterpret_cast<float*>(smem);   // [128][128] u tile (EPI 0)

    // ---- epilogue ----
    #pragma unroll
    for (int mt = 0; mt < 2; mt++) {
        #pragma unroll
        for (int h = 0; h < 2; h++) {
            const int ml = wm * 32 + mt * 16 + (lane >> 2) + h * 8;
            const size_t mg = mblock + ml;
            #pragma unroll
            for (int nt = 0; nt < 8; nt++) {
                const int nl = wn * 64 + nt * 8 + (lane & 3) * 2;
                const int n = nblock + nl;
                float v0 = acc[mt][nt][h * 2], v1 = acc[mt][nt][h * 2 + 1];
                if (EPI == 0) {
                    float2 o; o.x = v0; o.y = v1;
                    *reinterpret_cast<float2*>(Cf + mg * 256 + n) = o;
                    *reinterpret_cast<float2*>(su + ml * 128 + nl) = o;
                } else if (EPI == 1) {
                    uint32_t hv = *reinterpret_cast<const uint32_t*>(xn + mg * 256 + n);
                    __half2 xh = *reinterpret_cast<__half2*>(&hv);
                    float x0 = __half2float(__low2half(xh));
                    float x1 = __half2float(__high2half(xh));
                    float2 dd = *reinterpret_cast<const float2*>(auxf + n);
                    float o0 = gelu_tanh(v0 + dd.x * x0);
                    float o1 = gelu_tanh(v1 + dd.y * x1);
                    *reinterpret_cast<uint32_t*>(Cb + mg * 256 + n) = pk2h(o0, o1);
                } else {
                    float2 xv = *reinterpret_cast<const float2*>(auxx + mg * 256 + n);
                    float2 bb2 = *reinterpret_cast<const float2*>(auxf + n);
                    float2 o;
                    o.x = xv.x + v0 + bb2.x;
                    o.y = xv.y + v1 + bb2.y;
                    *reinterpret_cast<float2*>(Cf + mg * 256 + n) = o;
                }
            }
        }
    }

    if (EPI == 0) {
        // fused scanA: per-chunk Horner carries from the staged u tile.
        __syncthreads();
        const int s_loc = tid & 127;
        const int chl = tid >> 7;
        const int sg = nblock + s_loc;
        const float cc = g_coeff[sg];
        const float* col = su + chl * 64 * 128 + s_loc;
        float a = 0.0f;
        #pragma unroll 16
        for (int j = 0; j < 64; j++) a = fmaf(cc, a, col[j * 128]);
        const int b = (int)(mblock >> 12);
        const int chg = (int)((mblock & 4095) >> 6) + chl;
        g_carry[((size_t)b * NCH + chg) * SS + sg] = a;
    }
}

// ---------------- 3b. chunk-level scan (prefetch all carries) ----------------
__global__ void __launch_bounds__(256) scanB_kernel(const float* __restrict__ state0,
                                                    float* __restrict__ out) {
    int b = blockIdx.x, s = threadIdx.x;
    const float* cp = g_carry + (size_t)b * NCH * SS + s;
    float carr[NCH];
    #pragma unroll
    for (int ch = 0; ch < NCH; ch++) carr[ch] = cp[(size_t)ch * SS];
    float cL = g_cL[s];
    float run = state0[b * SS + s];
    float* s0 = g_S0 + (size_t)b * NCH * SS + s;
    #pragma unroll
    for (int ch = 0; ch < NCH; ch++) {
        s0[(size_t)ch * SS] = run;
        run = fmaf(cL, run, carr[ch]);
    }
    out[(size_t)MM * HH + (size_t)b * SS + s] = run;
}

// ---------------- 3c. re-scan, write states fp16 ----------------
__global__ void __launch_bounds__(256) scanC_kernel() {
    int b = blockIdx.y, ch = blockIdx.x, s = threadIdx.x;
    float c = g_coeff[s];
    float run = g_S0[((size_t)b * NCH + ch) * SS + s];
    size_t row0 = (size_t)(b * TT + ch * LCH);
    #pragma unroll 4
    for (int j = 0; j < LCH; j++) {
        size_t row = row0 + j;
        run = fmaf(c, run, g_u[row * SS + s]);
        g_st[row * 256 + s] = __float2half_rn(run);
    }
}

// ---------------- launch ----------------
extern "C" void kernel_launch(void* const* d_in, const int* in_sizes, int n_in,
                              void* d_out, int out_size) {
    const float* x       = (const float*)d_in[0];
    const float* state0  = (const float*)d_in[1];
    const float* its     = (const float*)d_in[2];
    const float* sth     = (const float*)d_in[3];
    const float* direct  = (const float*)d_in[4];
    const float* a_diag  = (const float*)d_in[5];
    const float* g_diag  = (const float*)d_in[6];
    const float* dt      = (const float*)d_in[7];
    const float* norm_w  = (const float*)d_in[8];
    const float* norm_b  = (const float*)d_in[9];
    const float* out_w   = (const float*)d_in[10];
    const float* out_b   = (const float*)d_in[11];
    float* out = (float*)d_out;

    __half *xn, *st, *mix, *wcat;
    float* u;
    cudaGetSymbolAddress((void**)&xn,   g_xn);
    cudaGetSymbolAddress((void**)&st,   g_st);
    cudaGetSymbolAddress((void**)&mix,  g_mix);
    cudaGetSymbolAddress((void**)&wcat, g_wcat);
    cudaGetSymbolAddress((void**)&u,    g_u);

    cudaFuncSetAttribute(gemm_mma<0>, cudaFuncAttributeMaxDynamicSharedMemorySize, GSMEM);
    cudaFuncSetAttribute(gemm_mma<1>, cudaFuncAttributeMaxDynamicSharedMemorySize, GSMEM);
    cudaFuncSetAttribute(gemm_mma<2>, cudaFuncAttributeMaxDynamicSharedMemorySize, GSMEM);

    wsplit_kernel<<<dim3(256, 3), 256>>>(its, sth, out_w, a_diag, g_diag, dt);
    ln_kernel<<<MM / 8, 256>>>(x, norm_w, norm_b);

    dim3 ggrid(2, MM / 128);   // N/128, M/128
    gemm_mma<0><<<ggrid, 256, GSMEM>>>(xn, wcat, u, nullptr, nullptr, nullptr, nullptr);

    scanB_kernel<<<BB, 256>>>(state0, out);
    scanC_kernel<<<dim3(NCH, BB), 256>>>();

    gemm_mma<1><<<ggrid, 256, GSMEM>>>(st, wcat + (size_t)1 * 256 * 256, nullptr, mix,
                                       direct, nullptr, xn);
    gemm_mma<2><<<ggrid, 256, GSMEM>>>(mix, wcat + (size_t)2 * 256 * 256, out, nullptr,
                                       out_b, x, nullptr);
}

// round 10
// speedup vs baseline: 4.5045x; 1.1624x over previous
#include <cuda_runtime.h>
#include <cuda_fp16.h>
#include <cstdint>
#include <cstddef>

#define BB 32
#define TT 4096
#define HH 256
#define SS 256
#define MM (BB*TT)          // 131072 tokens
#define NCH 64              // chunks over T
#define LCH 64              // chunk length

// ---------------- scratch (static device globals; no allocations) ----------------
__device__ __half g_xn[(size_t)MM*256];       // layernormed x (fp16)
__device__ __half g_mix[(size_t)MM*256];      // gelu(mixed) (fp16)
__device__ __half g_u[(size_t)MM*256];        // u (fp16)
__device__ __half g_wcat[(size_t)3*256*256];  // per-weight W (fp16)
__device__ float g_carry[(size_t)BB*NCH*SS];
__device__ float g_S0[(size_t)BB*NCH*SS];
__device__ float g_coeff[SS];
__device__ float g_cL[SS];

// ---------------- helpers ----------------
__device__ __forceinline__ uint32_t smem_u32(const void* p) {
    uint32_t a;
    asm("{ .reg .u64 t; cvta.to.shared.u64 t, %1; cvt.u32.u64 %0, t; }" : "=r"(a) : "l"(p));
    return a;
}
__device__ __forceinline__ float softplus_f(float x) {
    return fmaxf(x, 0.0f) + log1pf(expf(-fabsf(x)));
}
__device__ __forceinline__ float gelu_tanh(float x) {
    float x3 = x * x * x;
    float t = tanhf(0.7978845608028654f * (x + 0.044715f * x3));
    return 0.5f * x * (1.0f + t);
}
__device__ __forceinline__ unsigned pk2h(float a, float b) {
    __half2 t = __floats2half2_rn(a, b);
    return *reinterpret_cast<unsigned*>(&t);
}

#define CP_ASYNC16(saddr, gptr) \
    asm volatile("cp.async.cg.shared.global [%0], [%1], 16;" :: "r"(saddr), "l"(gptr))
#define CP_COMMIT() asm volatile("cp.async.commit_group;" ::: "memory")
#define CP_WAIT(n)  asm volatile("cp.async.wait_group %0;" :: "n"(n) : "memory")
#define LDMATRIX_X4(r, addr) \
    asm volatile("ldmatrix.sync.aligned.m8n8.x4.shared.b16 {%0,%1,%2,%3}, [%4];" \
        : "=r"((r)[0]), "=r"((r)[1]), "=r"((r)[2]), "=r"((r)[3]) : "r"(addr))
#define MMA_F16(d, a, b0, b1) \
    asm volatile("mma.sync.aligned.m16n8k16.row.col.f32.f16.f16.f32 " \
        "{%0,%1,%2,%3}, {%4,%5,%6,%7}, {%8,%9}, {%0,%1,%2,%3};" \
        : "+f"((d)[0]), "+f"((d)[1]), "+f"((d)[2]), "+f"((d)[3]) \
        : "r"((a)[0]), "r"((a)[1]), "r"((a)[2]), "r"((a)[3]), "r"(b0), "r"(b1))

#define GSLOT 18432

// ---------------- 0. wsplit (fp16) + coefficients ----------------
__global__ void wsplit_kernel(const float* __restrict__ its,
                              const float* __restrict__ sth,
                              const float* __restrict__ ow,
                              const float* __restrict__ a_diag,
                              const float* __restrict__ g_diag,
                              const float* __restrict__ dt) {
    int widx = blockIdx.y;
    int n = blockIdx.x;
    int k = threadIdx.x;
    if (widx == 0 && n == 0) {
        int s = k;
        float dt_s = softplus_f(dt[s]) + 1e-4f;
        float omega = a_diag[s] * dt_s;
        float decay = expf(-softplus_f(g_diag[s]) * dt_s);
        decay *= decay;
        float c = decay * cosf(omega);
        g_coeff[s] = c;
        float p = c;
        #pragma unroll
        for (int i = 0; i < 6; i++) p = p * p;
        g_cL[s] = p;
    }
    const float* W = (widx == 0) ? its : ((widx == 1) ? sth : ow);
    g_wcat[(size_t)widx * 256 * 256 + (size_t)n * 256 + k] = __float2half_rn(W[n * 256 + k]);
}

// ---------------- 1. layernorm -> fp16 ----------------
__global__ void __launch_bounds__(256) ln_kernel(const float* __restrict__ x,
                                                 const float* __restrict__ w,
                                                 const float* __restrict__ b) {
    int warp = threadIdx.x >> 5, lane = threadIdx.x & 31;
    size_t row = (size_t)blockIdx.x * 8 + warp;
    const float4* xr = reinterpret_cast<const float4*>(x + row * HH);
    float4 v0 = xr[lane];
    float4 v1 = xr[lane + 32];
    float sum = v0.x + v0.y + v0.z + v0.w + v1.x + v1.y + v1.z + v1.w;
    float sq  = v0.x*v0.x + v0.y*v0.y + v0.z*v0.z + v0.w*v0.w
              + v1.x*v1.x + v1.y*v1.y + v1.z*v1.z + v1.w*v1.w;
    #pragma unroll
    for (int o = 16; o > 0; o >>= 1) {
        sum += __shfl_xor_sync(0xffffffffu, sum, o);
        sq  += __shfl_xor_sync(0xffffffffu, sq,  o);
    }
    float mu = sum * (1.0f / HH);
    float var = sq * (1.0f / HH) - mu * mu;
    float rs = rsqrtf(var + 1e-5f);

    const float4* w4 = reinterpret_cast<const float4*>(w);
    const float4* b4 = reinterpret_cast<const float4*>(b);
    __half* dst = g_xn + row * 256;

    #pragma unroll
    for (int half_ = 0; half_ < 2; half_++) {
        float4 v = half_ ? v1 : v0;
        int c0 = half_ * 128 + lane * 4;
        float4 wv = w4[half_ * 32 + lane], bv = b4[half_ * 32 + lane];
        float r0 = (v.x - mu) * rs * wv.x + bv.x;
        float r1 = (v.y - mu) * rs * wv.y + bv.y;
        float r2 = (v.z - mu) * rs * wv.z + bv.z;
        float r3 = (v.w - mu) * rs * wv.w + bv.w;
        uint2 hv;
        hv.x = pk2h(r0, r1);
        hv.y = pk2h(r2, r3);
        *reinterpret_cast<uint2*>(dst + c0) = hv;
    }
}

// ---------------- 2. fp16 HMMA GEMM (EPI 0: ->u fp16 + carries; EPI 2: out) ----------
#define GSMEM (6*GSLOT)
template <int EPI>
__global__ void __launch_bounds__(256, 2) gemm_mma(
    const __half* __restrict__ A,
    const __half* __restrict__ W,
    float* __restrict__ Cf,
    __half* __restrict__ Cb,
    const float* __restrict__ auxf,
    const float* __restrict__ auxx)
{
    extern __shared__ __half smem[];
    const uint32_t sbase = smem_u32(smem);
    const int tid = threadIdx.x;
    const int lane = tid & 31, wid = tid >> 5;
    const int wm = wid & 3, wn = wid >> 2;
    const size_t mblock = (size_t)blockIdx.y * 128;
    const int nblock = blockIdx.x * 128;

    const int lrow = tid >> 3;
    const int lseg = (tid & 7) * 8;
    const __half* gA = A + (mblock + lrow) * 256 + lseg;
    const __half* gW = W + (size_t)(nblock + lrow) * 256 + lseg;
    const uint32_t sAw = sbase + (lrow * 72 + lseg) * 2;
    const uint32_t sBw = sbase + 3*GSLOT + (lrow * 72 + lseg) * 2;

    const uint32_t a_off = sbase + ((wm * 32 + (lane & 15)) * 72 + (lane >> 4) * 8) * 2;
    const uint32_t b_off = sbase + 3*GSLOT +
        ((wn * 64 + ((lane >> 3) & 1) * 8 + (lane & 7)) * 72 + (lane >> 4) * 8) * 2;

    float acc[2][8][4];
    #pragma unroll
    for (int i = 0; i < 2; i++)
        #pragma unroll
        for (int j = 0; j < 8; j++)
            #pragma unroll
            for (int q = 0; q < 4; q++) acc[i][j][q] = 0.0f;

    auto issue_step = [&](int s) {
        const uint32_t so = (uint32_t)(s % 3) * GSLOT;
        const int col = s * 64;
        #pragma unroll
        for (int p = 0; p < 4; p++)
            CP_ASYNC16(sAw + so + p * 4608, gA + (size_t)p * 32 * 256 + col);
        #pragma unroll
        for (int p = 0; p < 4; p++)
            CP_ASYNC16(sBw + so + p * 4608, gW + (size_t)p * 32 * 256 + col);
        CP_COMMIT();
    };

    issue_step(0);
    issue_step(1);

    #pragma unroll
    for (int s = 0; s < 4; s++) {
        if (s < 3) { CP_WAIT(1); } else { CP_WAIT(0); }
        __syncthreads();
        if (s < 2) issue_step(s + 2);
        const uint32_t ab = a_off + (uint32_t)(s % 3) * GSLOT;
        const uint32_t bb = b_off + (uint32_t)(s % 3) * GSLOT;
        #pragma unroll
        for (int ks = 0; ks < 4; ks++) {
            uint32_t af[2][4];
            LDMATRIX_X4(af[0], ab + ks * 32);
            LDMATRIX_X4(af[1], ab + 2304 + ks * 32);
            uint32_t bf[4][4];
            #pragma unroll
            for (int q = 0; q < 4; q++) LDMATRIX_X4(bf[q], bb + q * 2304 + ks * 32);
            #pragma unroll
            for (int mt = 0; mt < 2; mt++)
                #pragma unroll
                for (int nt = 0; nt < 8; nt++) {
                    const int q = nt >> 1, od = nt & 1;
                    MMA_F16(acc[mt][nt], af[mt], bf[q][od], bf[q][2 + od]);
                }
        }
    }

    if (EPI == 0) __syncthreads();
    float* su = reinterpret_cast<float*>(smem);   // [128][128] u tile (EPI 0)

    #pragma unroll
    for (int mt = 0; mt < 2; mt++) {
        #pragma unroll
        for (int h = 0; h < 2; h++) {
            const int ml = wm * 32 + mt * 16 + (lane >> 2) + h * 8;
            const size_t mg = mblock + ml;
            #pragma unroll
            for (int nt = 0; nt < 8; nt++) {
                const int nl = wn * 64 + nt * 8 + (lane & 3) * 2;
                const int n = nblock + nl;
                float v0 = acc[mt][nt][h * 2], v1 = acc[mt][nt][h * 2 + 1];
                if (EPI == 0) {
                    *reinterpret_cast<uint32_t*>(Cb + mg * 256 + n) = pk2h(v0, v1);
                    float2 o; o.x = v0; o.y = v1;
                    *reinterpret_cast<float2*>(su + ml * 128 + nl) = o;
                } else {
                    float2 xv = *reinterpret_cast<const float2*>(auxx + mg * 256 + n);
                    float2 bb2 = *reinterpret_cast<const float2*>(auxf + n);
                    float2 o;
                    o.x = xv.x + v0 + bb2.x;
                    o.y = xv.y + v1 + bb2.y;
                    *reinterpret_cast<float2*>(Cf + mg * 256 + n) = o;
                }
            }
        }
    }

    if (EPI == 0) {
        __syncthreads();
        const int s_loc = tid & 127;
        const int chl = tid >> 7;
        const int sg = nblock + s_loc;
        const float cc = g_coeff[sg];
        const float* col = su + chl * 64 * 128 + s_loc;
        float a = 0.0f;
        #pragma unroll 16
        for (int j = 0; j < 64; j++) a = fmaf(cc, a, col[j * 128]);
        const int b = (int)(mblock >> 12);
        const int chg = (int)((mblock & 4095) >> 6) + chl;
        g_carry[((size_t)b * NCH + chg) * SS + sg] = a;
    }
}

// ---------------- 2b. gemm1 with fused chunk-scan (u -> st in place -> MMA) --------
// A slots 0,1 (scanned st); W slots 2,3,4. 5*GSLOT = 92160 B. 2 CTAs/SM.
#define GSMEM1 (5*GSLOT)
__global__ void __launch_bounds__(256, 2) gemm1_fused(
    const __half* __restrict__ U,
    const __half* __restrict__ W,
    __half* __restrict__ Cb,
    const float* __restrict__ direct,
    const __half* __restrict__ xn)
{
    extern __shared__ __half smem[];
    const uint32_t sbase = smem_u32(smem);
    const int tid = threadIdx.x;
    const int lane = tid & 31, wid = tid >> 5;
    const int wm = wid & 3, wn = wid >> 2;
    const size_t mblock = (size_t)blockIdx.y * 128;
    const int nblock = blockIdx.x * 128;

    const int lrow = tid >> 3;
    const int lseg = (tid & 7) * 8;
    const __half* gU = U + (mblock + lrow) * 256 + lseg;
    const __half* gW = W + (size_t)(nblock + lrow) * 256 + lseg;
    const uint32_t sAw = sbase + (lrow * 72 + lseg) * 2;
    const uint32_t sBw = sbase + 2*GSLOT + (lrow * 72 + lseg) * 2;

    const uint32_t a_off = sbase + ((wm * 32 + (lane & 15)) * 72 + (lane >> 4) * 8) * 2;
    const uint32_t b_off = sbase + 2*GSLOT +
        ((wn * 64 + ((lane >> 3) & 1) * 8 + (lane & 7)) * 72 + (lane >> 4) * 8) * 2;

    // scan setup: 128 chains (64 cols x 2 row-chunks) per K-chunk
    const int sc = tid & 63, sh = (tid >> 6) & 1;
    const bool scanner = tid < 128;
    float s0v[4], cfv[4];
    if (scanner) {
        const int bidx = (int)(mblock >> 12);
        const int chg = (int)((mblock & 4095) >> 6) + sh;
        #pragma unroll
        for (int s = 0; s < 4; s++) {
            const int scol = s * 64 + sc;
            cfv[s] = g_coeff[scol];
            s0v[s] = g_S0[((size_t)bidx * NCH + chg) * SS + scol];
        }
    }

    float acc[2][8][4];
    #pragma unroll
    for (int i = 0; i < 2; i++)
        #pragma unroll
        for (int j = 0; j < 8; j++)
            #pragma unroll
            for (int q = 0; q < 4; q++) acc[i][j][q] = 0.0f;

    auto issue_u = [&](int s) {
        const uint32_t so = (uint32_t)(s & 1) * GSLOT;
        #pragma unroll
        for (int p = 0; p < 4; p++)
            CP_ASYNC16(sAw + so + p * 4608, gU + (size_t)p * 32 * 256 + s * 64);
    };
    auto issue_w = [&](int s) {
        const uint32_t so = (uint32_t)(s % 3) * GSLOT;
        #pragma unroll
        for (int p = 0; p < 4; p++)
            CP_ASYNC16(sBw + so + p * 4608, gW + (size_t)p * 32 * 256 + s * 64);
    };
    auto scan = [&](int s) {
        if (scanner) {
            __half* ap = smem + (size_t)(s & 1) * (GSLOT / 2) + sh * 64 * 72 + sc;
            float run = s0v[s];
            const float cc = cfv[s];
            #pragma unroll
            for (int j = 0; j < 64; j++) {
                run = fmaf(cc, run, __half2float(ap[j * 72]));
                ap[j * 72] = __float2half_rn(run);
            }
        }
    };

    // prologue: u0+W0 (group0), W1 (group1)
    issue_u(0); issue_w(0); CP_COMMIT();
    issue_w(1); CP_COMMIT();
    CP_WAIT(1);            // group0 done (u0, W0)
    __syncthreads();
    scan(0);

    #pragma unroll
    for (int s = 0; s < 4; s++) {
        __syncthreads();                       // all prior readers of reused slots done
        if (s < 3) {
            issue_u(s + 1);                    // into A slot (s+1)&1 (reader MMA(s-1) done)
            if (s < 2) issue_w(s + 2);         // into W slot (s+2)%3 (reader MMA(s-1) done)
            CP_COMMIT();
        }
        const uint32_t ab = a_off + (uint32_t)(s & 1) * GSLOT;
        const uint32_t bb = b_off + (uint32_t)(s % 3) * GSLOT;
        #pragma unroll
        for (int ks = 0; ks < 4; ks++) {
            uint32_t af[2][4];
            LDMATRIX_X4(af[0], ab + ks * 32);
            LDMATRIX_X4(af[1], ab + 2304 + ks * 32);
            uint32_t bf[4][4];
            #pragma unroll
            for (int q = 0; q < 4; q++) LDMATRIX_X4(bf[q], bb + q * 2304 + ks * 32);
            #pragma unroll
            for (int mt = 0; mt < 2; mt++)
                #pragma unroll
                for (int nt = 0; nt < 8; nt++) {
                    const int q = nt >> 1, od = nt & 1;
                    MMA_F16(acc[mt][nt], af[mt], bf[q][od], bf[q][2 + od]);
                }
        }
        if (s < 3) {
            CP_WAIT(0);                        // everything in flight complete
            __syncthreads();                   // cross-thread cp.async visibility
            scan(s + 1);                       // transform u(s+1) -> st in place
        }
    }

    // epilogue: mix = gelu(acc + direct[n]*xn) -> fp16
    #pragma unroll
    for (int mt = 0; mt < 2; mt++) {
        #pragma unroll
        for (int h = 0; h < 2; h++) {
            const size_t mg = mblock + wm * 32 + mt * 16 + (lane >> 2) + h * 8;
            #pragma unroll
            for (int nt = 0; nt < 8; nt++) {
                const int n = nblock + wn * 64 + nt * 8 + (lane & 3) * 2;
                float v0 = acc[mt][nt][h * 2], v1 = acc[mt][nt][h * 2 + 1];
                uint32_t hv = *reinterpret_cast<const uint32_t*>(xn + mg * 256 + n);
                __half2 xh = *reinterpret_cast<__half2*>(&hv);
                float x0 = __half2float(__low2half(xh));
                float x1 = __half2float(__high2half(xh));
                float2 dd = *reinterpret_cast<const float2*>(direct + n);
                float o0 = gelu_tanh(v0 + dd.x * x0);
                float o1 = gelu_tanh(v1 + dd.y * x1);
                *reinterpret_cast<uint32_t*>(Cb + mg * 256 + n) = pk2h(o0, o1);
            }
        }
    }
}

// ---------------- 3b. chunk-level scan (prefetch all carries) ----------------
__global__ void __launch_bounds__(256) scanB_kernel(const float* __restrict__ state0,
                                                    float* __restrict__ out) {
    int b = blockIdx.x, s = threadIdx.x;
    const float* cp = g_carry + (size_t)b * NCH * SS + s;
    float carr[NCH];
    #pragma unroll
    for (int ch = 0; ch < NCH; ch++) carr[ch] = cp[(size_t)ch * SS];
    float cL = g_cL[s];
    float run = state0[b * SS + s];
    float* s0 = g_S0 + (size_t)b * NCH * SS + s;
    #pragma unroll
    for (int ch = 0; ch < NCH; ch++) {
        s0[(size_t)ch * SS] = run;
        run = fmaf(cL, run, carr[ch]);
    }
    out[(size_t)MM * HH + (size_t)b * SS + s] = run;
}

// ---------------- launch ----------------
extern "C" void kernel_launch(void* const* d_in, const int* in_sizes, int n_in,
                              void* d_out, int out_size) {
    const float* x       = (const float*)d_in[0];
    const float* state0  = (const float*)d_in[1];
    const float* its     = (const float*)d_in[2];
    const float* sth     = (const float*)d_in[3];
    const float* direct  = (const float*)d_in[4];
    const float* a_diag  = (const float*)d_in[5];
    const float* g_diag  = (const float*)d_in[6];
    const float* dt      = (const float*)d_in[7];
    const float* norm_w  = (const float*)d_in[8];
    const float* norm_b  = (const float*)d_in[9];
    const float* out_w   = (const float*)d_in[10];
    const float* out_b   = (const float*)d_in[11];
    float* out = (float*)d_out;

    __half *xn, *mix, *u16, *wcat;
    cudaGetSymbolAddress((void**)&xn,   g_xn);
    cudaGetSymbolAddress((void**)&mix,  g_mix);
    cudaGetSymbolAddress((void**)&u16,  g_u);
    cudaGetSymbolAddress((void**)&wcat, g_wcat);

    cudaFuncSetAttribute(gemm_mma<0>, cudaFuncAttributeMaxDynamicSharedMemorySize, GSMEM);
    cudaFuncSetAttribute(gemm_mma<2>, cudaFuncAttributeMaxDynamicSharedMemorySize, GSMEM);
    cudaFuncSetAttribute(gemm1_fused, cudaFuncAttributeMaxDynamicSharedMemorySize, GSMEM1);

    wsplit_kernel<<<dim3(256, 3), 256>>>(its, sth, out_w, a_diag, g_diag, dt);
    ln_kernel<<<MM / 8, 256>>>(x, norm_w, norm_b);

    dim3 ggrid(2, MM / 128);   // N/128, M/128
    gemm_mma<0><<<ggrid, 256, GSMEM>>>(xn, wcat, nullptr, u16, nullptr, nullptr);

    scanB_kernel<<<BB, 256>>>(state0, out);

    gemm1_fused<<<ggrid, 256, GSMEM1>>>(u16, wcat + (size_t)1 * 256 * 256, mix, direct, xn);

    gemm_mma<2><<<ggrid, 256, GSMEM>>>(mix, wcat + (size_t)2 * 256 * 256, out, nullptr,
                                       out_b, x);
}

// round 11
// speedup vs baseline: 4.5395x; 1.0078x over previous
#include <cuda_runtime.h>
#include <cuda_fp16.h>
#include <cstdint>
#include <cstddef>

#define BB 32
#define TT 4096
#define HH 256
#define SS 256
#define MM (BB*TT)          // 131072 tokens
#define NCH 64              // chunks over T
#define LCH 64              // chunk length

// ---------------- scratch (static device globals; no allocations) ----------------
__device__ __half g_xn[(size_t)MM*256];       // layernormed x (fp16)
__device__ __half g_u[(size_t)MM*256];        // u (fp16)
__device__ __half g_wcat[(size_t)3*256*256];  // per-weight W (fp16)
__device__ float g_carry[(size_t)BB*NCH*SS];
__device__ float g_S0[(size_t)BB*NCH*SS];
__device__ float g_coeff[SS];
__device__ float g_cL[SS];

// ---------------- helpers ----------------
__device__ __forceinline__ uint32_t smem_u32(const void* p) {
    uint32_t a;
    asm("{ .reg .u64 t; cvta.to.shared.u64 t, %1; cvt.u32.u64 %0, t; }" : "=r"(a) : "l"(p));
    return a;
}
__device__ __forceinline__ float softplus_f(float x) {
    return fmaxf(x, 0.0f) + log1pf(expf(-fabsf(x)));
}
__device__ __forceinline__ float gelu_tanh(float x) {
    float x3 = x * x * x;
    float t = tanhf(0.7978845608028654f * (x + 0.044715f * x3));
    return 0.5f * x * (1.0f + t);
}
__device__ __forceinline__ unsigned pk2h(float a, float b) {
    __half2 t = __floats2half2_rn(a, b);
    return *reinterpret_cast<unsigned*>(&t);
}

#define CP_ASYNC16(saddr, gptr) \
    asm volatile("cp.async.cg.shared.global [%0], [%1], 16;" :: "r"(saddr), "l"(gptr))
#define CP_COMMIT() asm volatile("cp.async.commit_group;" ::: "memory")
#define CP_WAIT(n)  asm volatile("cp.async.wait_group %0;" :: "n"(n) : "memory")
#define LDMATRIX_X4(r, addr) \
    asm volatile("ldmatrix.sync.aligned.m8n8.x4.shared.b16 {%0,%1,%2,%3}, [%4];" \
        : "=r"((r)[0]), "=r"((r)[1]), "=r"((r)[2]), "=r"((r)[3]) : "r"(addr))
#define MMA_F16(d, a, b0, b1) \
    asm volatile("mma.sync.aligned.m16n8k16.row.col.f32.f16.f16.f32 " \
        "{%0,%1,%2,%3}, {%4,%5,%6,%7}, {%8,%9}, {%0,%1,%2,%3};" \
        : "+f"((d)[0]), "+f"((d)[1]), "+f"((d)[2]), "+f"((d)[3]) \
        : "r"((a)[0]), "r"((a)[1]), "r"((a)[2]), "r"((a)[3]), "r"(b0), "r"(b1))

#define GSLOT 18432

// ---------------- 0. wsplit (fp16) + coefficients ----------------
__global__ void wsplit_kernel(const float* __restrict__ its,
                              const float* __restrict__ sth,
                              const float* __restrict__ ow,
                              const float* __restrict__ a_diag,
                              const float* __restrict__ g_diag,
                              const float* __restrict__ dt) {
    int widx = blockIdx.y;
    int n = blockIdx.x;
    int k = threadIdx.x;
    if (widx == 0 && n == 0) {
        int s = k;
        float dt_s = softplus_f(dt[s]) + 1e-4f;
        float omega = a_diag[s] * dt_s;
        float decay = expf(-softplus_f(g_diag[s]) * dt_s);
        decay *= decay;
        float c = decay * cosf(omega);
        g_coeff[s] = c;
        float p = c;
        #pragma unroll
        for (int i = 0; i < 6; i++) p = p * p;
        g_cL[s] = p;
    }
    const float* W = (widx == 0) ? its : ((widx == 1) ? sth : ow);
    g_wcat[(size_t)widx * 256 * 256 + (size_t)n * 256 + k] = __float2half_rn(W[n * 256 + k]);
}

// ---------------- 1. layernorm -> fp16 ----------------
__global__ void __launch_bounds__(256) ln_kernel(const float* __restrict__ x,
                                                 const float* __restrict__ w,
                                                 const float* __restrict__ b) {
    int warp = threadIdx.x >> 5, lane = threadIdx.x & 31;
    size_t row = (size_t)blockIdx.x * 8 + warp;
    const float4* xr = reinterpret_cast<const float4*>(x + row * HH);
    float4 v0 = xr[lane];
    float4 v1 = xr[lane + 32];
    float sum = v0.x + v0.y + v0.z + v0.w + v1.x + v1.y + v1.z + v1.w;
    float sq  = v0.x*v0.x + v0.y*v0.y + v0.z*v0.z + v0.w*v0.w
              + v1.x*v1.x + v1.y*v1.y + v1.z*v1.z + v1.w*v1.w;
    #pragma unroll
    for (int o = 16; o > 0; o >>= 1) {
        sum += __shfl_xor_sync(0xffffffffu, sum, o);
        sq  += __shfl_xor_sync(0xffffffffu, sq,  o);
    }
    float mu = sum * (1.0f / HH);
    float var = sq * (1.0f / HH) - mu * mu;
    float rs = rsqrtf(var + 1e-5f);

    const float4* w4 = reinterpret_cast<const float4*>(w);
    const float4* b4 = reinterpret_cast<const float4*>(b);
    __half* dst = g_xn + row * 256;

    #pragma unroll
    for (int half_ = 0; half_ < 2; half_++) {
        float4 v = half_ ? v1 : v0;
        int c0 = half_ * 128 + lane * 4;
        float4 wv = w4[half_ * 32 + lane], bv = b4[half_ * 32 + lane];
        float r0 = (v.x - mu) * rs * wv.x + bv.x;
        float r1 = (v.y - mu) * rs * wv.y + bv.y;
        float r2 = (v.z - mu) * rs * wv.z + bv.z;
        float r3 = (v.w - mu) * rs * wv.w + bv.w;
        uint2 hv;
        hv.x = pk2h(r0, r1);
        hv.y = pk2h(r2, r3);
        *reinterpret_cast<uint2*>(dst + c0) = hv;
    }
}

// ---------------- 2. gemm0: xn x W0 -> u fp16 + fused chunk carries ----------------
#define GSMEM0 (6*GSLOT)
__global__ void __launch_bounds__(256, 2) gemm0_kernel(
    const __half* __restrict__ A,
    const __half* __restrict__ W,
    __half* __restrict__ Cb)
{
    extern __shared__ __half smem[];
    const uint32_t sbase = smem_u32(smem);
    const int tid = threadIdx.x;
    const int lane = tid & 31, wid = tid >> 5;
    const int wm = wid & 3, wn = wid >> 2;
    const size_t mblock = (size_t)blockIdx.y * 128;
    const int nblock = blockIdx.x * 128;

    const int lrow = tid >> 3;
    const int lseg = (tid & 7) * 8;
    const __half* gA = A + (mblock + lrow) * 256 + lseg;
    const __half* gW = W + (size_t)(nblock + lrow) * 256 + lseg;
    const uint32_t sAw = sbase + (lrow * 72 + lseg) * 2;
    const uint32_t sBw = sbase + 3*GSLOT + (lrow * 72 + lseg) * 2;

    const uint32_t a_off = sbase + ((wm * 32 + (lane & 15)) * 72 + (lane >> 4) * 8) * 2;
    const uint32_t b_off = sbase + 3*GSLOT +
        ((wn * 64 + ((lane >> 3) & 1) * 8 + (lane & 7)) * 72 + (lane >> 4) * 8) * 2;

    float acc[2][8][4];
    #pragma unroll
    for (int i = 0; i < 2; i++)
        #pragma unroll
        for (int j = 0; j < 8; j++)
            #pragma unroll
            for (int q = 0; q < 4; q++) acc[i][j][q] = 0.0f;

    auto issue_step = [&](int s) {
        const uint32_t so = (uint32_t)(s % 3) * GSLOT;
        const int col = s * 64;
        #pragma unroll
        for (int p = 0; p < 4; p++)
            CP_ASYNC16(sAw + so + p * 4608, gA + (size_t)p * 32 * 256 + col);
        #pragma unroll
        for (int p = 0; p < 4; p++)
            CP_ASYNC16(sBw + so + p * 4608, gW + (size_t)p * 32 * 256 + col);
        CP_COMMIT();
    };

    issue_step(0);
    issue_step(1);

    #pragma unroll
    for (int s = 0; s < 4; s++) {
        if (s < 3) { CP_WAIT(1); } else { CP_WAIT(0); }
        __syncthreads();
        if (s < 2) issue_step(s + 2);
        const uint32_t ab = a_off + (uint32_t)(s % 3) * GSLOT;
        const uint32_t bb = b_off + (uint32_t)(s % 3) * GSLOT;
        #pragma unroll
        for (int ks = 0; ks < 4; ks++) {
            uint32_t af[2][4];
            LDMATRIX_X4(af[0], ab + ks * 32);
            LDMATRIX_X4(af[1], ab + 2304 + ks * 32);
            uint32_t bf[4][4];
            #pragma unroll
            for (int q = 0; q < 4; q++) LDMATRIX_X4(bf[q], bb + q * 2304 + ks * 32);
            #pragma unroll
            for (int mt = 0; mt < 2; mt++)
                #pragma unroll
                for (int nt = 0; nt < 8; nt++) {
                    const int q = nt >> 1, od = nt & 1;
                    MMA_F16(acc[mt][nt], af[mt], bf[q][od], bf[q][2 + od]);
                }
        }
    }

    __syncthreads();
    float* su = reinterpret_cast<float*>(smem);   // [128][128] u tile

    #pragma unroll
    for (int mt = 0; mt < 2; mt++) {
        #pragma unroll
        for (int h = 0; h < 2; h++) {
            const int ml = wm * 32 + mt * 16 + (lane >> 2) + h * 8;
            const size_t mg = mblock + ml;
            #pragma unroll
            for (int nt = 0; nt < 8; nt++) {
                const int nl = wn * 64 + nt * 8 + (lane & 3) * 2;
                const int n = nblock + nl;
                float v0 = acc[mt][nt][h * 2], v1 = acc[mt][nt][h * 2 + 1];
                *reinterpret_cast<uint32_t*>(Cb + mg * 256 + n) = pk2h(v0, v1);
                float2 o; o.x = v0; o.y = v1;
                *reinterpret_cast<float2*>(su + ml * 128 + nl) = o;
            }
        }
    }

    __syncthreads();
    const int s_loc = tid & 127;
    const int chl = tid >> 7;
    const int sg = nblock + s_loc;
    const float cc = g_coeff[sg];
    const float* col = su + chl * 64 * 128 + s_loc;
    float a = 0.0f;
    #pragma unroll 16
    for (int j = 0; j < 64; j++) a = fmaf(cc, a, col[j * 128]);
    const int b = (int)(mblock >> 12);
    const int chg = (int)((mblock & 4095) >> 6) + chl;
    g_carry[((size_t)b * NCH + chg) * SS + sg] = a;
}

// ---------------- 2b. mega kernel: scan-fused gemm1 (BN=256) + gemm2 ----------------
// Phase 1: u -> st (in-SMEM scan) -> MMA W1 -> gelu(+direct*xn) -> mix in SMEM.
// Phase 2: mix (SMEM A) x W2 -> out = x + acc + out_b.
// SMEM layout (bytes): A u/st slots 0,18432; mix slots 36864+i*18432 (i=0..3);
// W slots (256x64) 110592+i*36864 (i=0..2). Total 221184. 512 thr, 1 CTA/SM.
#define MIXB  (2*GSLOT)
#define WBASE (6*GSLOT)
#define WSLOT (2*GSLOT)
#define GSMEM12 (12*GSLOT)
__global__ void __launch_bounds__(512, 1) gemm12_kernel(
    const __half* __restrict__ U,
    const __half* __restrict__ W1,
    const __half* __restrict__ W2,
    const float* __restrict__ direct,
    const __half* __restrict__ xn,
    const float* __restrict__ x,
    const float* __restrict__ out_b,
    float* __restrict__ out)
{
    extern __shared__ __half smem[];
    const uint32_t sbase = smem_u32(smem);
    const int tid = threadIdx.x;
    const int lane = tid & 31, wid = tid >> 5;
    const int wm = wid & 3, wn = wid >> 2;       // wn 0..3
    const size_t mblock = (size_t)blockIdx.x * 128;

    // loaders: arow 0..63 (+64 per p), aseg = 8-half segment
    const int arow = tid >> 3;
    const int aseg = (tid & 7) * 8;
    const __half* gU  = U  + (mblock + arow) * 256 + aseg;
    const __half* gW1 = W1 + (size_t)arow * 256 + aseg;
    const __half* gW2 = W2 + (size_t)arow * 256 + aseg;
    const uint32_t sAw = sbase + (arow * 72 + aseg) * 2;
    const uint32_t sWw = sbase + WBASE + (arow * 72 + aseg) * 2;

    const uint32_t a_rel = ((wm * 32 + (lane & 15)) * 72 + (lane >> 4) * 8) * 2;
    const uint32_t b_off = sbase + WBASE +
        ((wn * 64 + ((lane >> 3) & 1) * 8 + (lane & 7)) * 72 + (lane >> 4) * 8) * 2;

    // scan setup: 128 chains (64 cols x 2 row-chunks) per K-chunk
    const int sc = tid & 63, sh = (tid >> 6) & 1;
    const bool scanner = tid < 128;
    float s0v[4], cfv[4];
    if (scanner) {
        const int bidx = (int)(mblock >> 12);
        const int chg = (int)((mblock & 4095) >> 6) + sh;
        #pragma unroll
        for (int s = 0; s < 4; s++) {
            const int scol = s * 64 + sc;
            cfv[s] = g_coeff[scol];
            s0v[s] = g_S0[((size_t)bidx * NCH + chg) * SS + scol];
        }
    }

    float acc[2][8][4];
    #pragma unroll
    for (int i = 0; i < 2; i++)
        #pragma unroll
        for (int j = 0; j < 8; j++)
            #pragma unroll
            for (int q = 0; q < 4; q++) acc[i][j][q] = 0.0f;

    auto issue_u = [&](int s) {
        const uint32_t so = (uint32_t)(s & 1) * GSLOT;
        #pragma unroll
        for (int p = 0; p < 2; p++)
            CP_ASYNC16(sAw + so + p * 9216, gU + (size_t)p * 64 * 256 + s * 64);
    };
    auto issue_w = [&](const __half* gWb, int s) {
        const uint32_t so = (uint32_t)(s % 3) * WSLOT;
        #pragma unroll
        for (int p = 0; p < 4; p++)
            CP_ASYNC16(sWw + so + p * 9216, gWb + (size_t)p * 64 * 256 + s * 64);
    };
    auto scan = [&](int s) {
        if (scanner) {
            __half* ap = smem + (size_t)(s & 1) * (GSLOT / 2) + sh * 64 * 72 + sc;
            float run = s0v[s];
            const float cc = cfv[s];
            #pragma unroll
            for (int j = 0; j < 64; j++) {
                run = fmaf(cc, run, __half2float(ap[j * 72]));
                ap[j * 72] = __float2half_rn(run);
            }
        }
    };

    // ---- phase 1 ----
    issue_u(0); issue_w(gW1, 0); CP_COMMIT();
    issue_w(gW1, 1); CP_COMMIT();
    CP_WAIT(1);
    __syncthreads();
    scan(0);

    #pragma unroll
    for (int s = 0; s < 4; s++) {
        __syncthreads();
        if (s < 3) {
            issue_u(s + 1);
            if (s < 2) issue_w(gW1, s + 2);
            CP_COMMIT();
        }
        const uint32_t ab = sbase + (uint32_t)(s & 1) * GSLOT + a_rel;
        const uint32_t bb = b_off + (uint32_t)(s % 3) * WSLOT;
        #pragma unroll
        for (int ks = 0; ks < 4; ks++) {
            uint32_t af[2][4];
            LDMATRIX_X4(af[0], ab + ks * 32);
            LDMATRIX_X4(af[1], ab + 2304 + ks * 32);
            uint32_t bf[4][4];
            #pragma unroll
            for (int q = 0; q < 4; q++) LDMATRIX_X4(bf[q], bb + q * 2304 + ks * 32);
            #pragma unroll
            for (int mt = 0; mt < 2; mt++)
                #pragma unroll
                for (int nt = 0; nt < 8; nt++) {
                    const int q = nt >> 1, od = nt & 1;
                    MMA_F16(acc[mt][nt], af[mt], bf[q][od], bf[q][2 + od]);
                }
        }
        if (s < 3) {
            CP_WAIT(0);
            __syncthreads();
            scan(s + 1);
        }
    }

    // all W-slot readers done before W2 prefetch overwrites ring slots
    __syncthreads();
    issue_w(gW2, 0); CP_COMMIT();
    issue_w(gW2, 1); CP_COMMIT();

    // ---- epilogue 1: mix = gelu(acc + direct*xn) -> SMEM (ldmatrix layout) ----
    char* smc = reinterpret_cast<char*>(smem);
    #pragma unroll
    for (int mt = 0; mt < 2; mt++) {
        #pragma unroll
        for (int h = 0; h < 2; h++) {
            const int ml = wm * 32 + mt * 16 + (lane >> 2) + h * 8;
            const size_t mg = mblock + ml;
            #pragma unroll
            for (int nt = 0; nt < 8; nt++) {
                const int nl = wn * 64 + nt * 8 + (lane & 3) * 2;
                float v0 = acc[mt][nt][h * 2], v1 = acc[mt][nt][h * 2 + 1];
                uint32_t hv = *reinterpret_cast<const uint32_t*>(xn + mg * 256 + nl);
                __half2 xh = *reinterpret_cast<__half2*>(&hv);
                float x0 = __half2float(__low2half(xh));
                float x1 = __half2float(__high2half(xh));
                float2 dd = *reinterpret_cast<const float2*>(direct + nl);
                float o0 = gelu_tanh(v0 + dd.x * x0);
                float o1 = gelu_tanh(v1 + dd.y * x1);
                *reinterpret_cast<uint32_t*>(
                    smc + MIXB + (nl >> 6) * GSLOT + (ml * 72 + (nl & 63)) * 2) = pk2h(o0, o1);
            }
        }
    }

    // re-zero acc for phase 2
    #pragma unroll
    for (int i = 0; i < 2; i++)
        #pragma unroll
        for (int j = 0; j < 8; j++)
            #pragma unroll
            for (int q = 0; q < 4; q++) acc[i][j][q] = 0.0f;

    // ---- phase 2: mix (SMEM) x W2 ----
    #pragma unroll
    for (int s = 0; s < 4; s++) {
        if (s < 3) { CP_WAIT(1); } else { CP_WAIT(0); }
        __syncthreads();
        if (s < 2) { issue_w(gW2, s + 2); CP_COMMIT(); }
        const uint32_t ab = sbase + MIXB + (uint32_t)s * GSLOT + a_rel;
        const uint32_t bb = b_off + (uint32_t)(s % 3) * WSLOT;
        #pragma unroll
        for (int ks = 0; ks < 4; ks++) {
            uint32_t af[2][4];
            LDMATRIX_X4(af[0], ab + ks * 32);
            LDMATRIX_X4(af[1], ab + 2304 + ks * 32);
            uint32_t bf[4][4];
            #pragma unroll
            for (int q = 0; q < 4; q++) LDMATRIX_X4(bf[q], bb + q * 2304 + ks * 32);
            #pragma unroll
            for (int mt = 0; mt < 2; mt++)
                #pragma unroll
                for (int nt = 0; nt < 8; nt++) {
                    const int q = nt >> 1, od = nt & 1;
                    MMA_F16(acc[mt][nt], af[mt], bf[q][od], bf[q][2 + od]);
                }
        }
    }

    // ---- epilogue 2: out = x + acc + out_b ----
    #pragma unroll
    for (int mt = 0; mt < 2; mt++) {
        #pragma unroll
        for (int h = 0; h < 2; h++) {
            const size_t mg = mblock + wm * 32 + mt * 16 + (lane >> 2) + h * 8;
            #pragma unroll
            for (int nt = 0; nt < 8; nt++) {
                const int n = wn * 64 + nt * 8 + (lane & 3) * 2;
                float v0 = acc[mt][nt][h * 2], v1 = acc[mt][nt][h * 2 + 1];
                float2 xv = *reinterpret_cast<const float2*>(x + mg * 256 + n);
                float2 bb2 = *reinterpret_cast<const float2*>(out_b + n);
                float2 o;
                o.x = xv.x + v0 + bb2.x;
                o.y = xv.y + v1 + bb2.y;
                *reinterpret_cast<float2*>(out + mg * 256 + n) = o;
            }
        }
    }
}

// ---------------- 3b. chunk-level scan (prefetch all carries) ----------------
__global__ void __launch_bounds__(256) scanB_kernel(const float* __restrict__ state0,
                                                    float* __restrict__ out) {
    int b = blockIdx.x, s = threadIdx.x;
    const float* cp = g_carry + (size_t)b * NCH * SS + s;
    float carr[NCH];
    #pragma unroll
    for (int ch = 0; ch < NCH; ch++) carr[ch] = cp[(size_t)ch * SS];
    float cL = g_cL[s];
    float run = state0[b * SS + s];
    float* s0 = g_S0 + (size_t)b * NCH * SS + s;
    #pragma unroll
    for (int ch = 0; ch < NCH; ch++) {
        s0[(size_t)ch * SS] = run;
        run = fmaf(cL, run, carr[ch]);
    }
    out[(size_t)MM * HH + (size_t)b * SS + s] = run;
}

// ---------------- launch ----------------
extern "C" void kernel_launch(void* const* d_in, const int* in_sizes, int n_in,
                              void* d_out, int out_size) {
    const float* x       = (const float*)d_in[0];
    const float* state0  = (const float*)d_in[1];
    const float* its     = (const float*)d_in[2];
    const float* sth     = (const float*)d_in[3];
    const float* direct  = (const float*)d_in[4];
    const float* a_diag  = (const float*)d_in[5];
    const float* g_diag  = (const float*)d_in[6];
    const float* dt      = (const float*)d_in[7];
    const float* norm_w  = (const float*)d_in[8];
    const float* norm_b  = (const float*)d_in[9];
    const float* out_w   = (const float*)d_in[10];
    const float* out_b   = (const float*)d_in[11];
    float* out = (float*)d_out;

    __half *xn, *u16, *wcat;
    cudaGetSymbolAddress((void**)&xn,   g_xn);
    cudaGetSymbolAddress((void**)&u16,  g_u);
    cudaGetSymbolAddress((void**)&wcat, g_wcat);

    cudaFuncSetAttribute(gemm0_kernel, cudaFuncAttributeMaxDynamicSharedMemorySize, GSMEM0);
    cudaFuncSetAttribute(gemm12_kernel, cudaFuncAttributeMaxDynamicSharedMemorySize, GSMEM12);

    wsplit_kernel<<<dim3(256, 3), 256>>>(its, sth, out_w, a_diag, g_diag, dt);
    ln_kernel<<<MM / 8, 256>>>(x, norm_w, norm_b);

    gemm0_kernel<<<dim3(2, MM / 128), 256, GSMEM0>>>(xn, wcat, u16);

    scanB_kernel<<<BB, 256>>>(state0, out);

    gemm12_kernel<<<MM / 128, 512, GSMEM12>>>(
        u16, wcat + (size_t)1 * 256 * 256, wcat + (size_t)2 * 256 * 256,
        direct, xn, x, out_b, out);
}